// round 5
// baseline (speedup 1.0000x reference)
#include <cuda_runtime.h>
#include <cstdint>

static constexpr int B_ = 8, T_ = 2048, S_ = 2048, H_ = 64;
static constexpr int NT = 256;

// smem float offsets: double-buffered raw K/V tiles, stride 72 (64 data + 8 pad)
static constexpr int KBUF0 = 0;
static constexpr int VBUF0 = 9216;
static constexpr int KBUF1 = 18432;
static constexpr int VBUF1 = 27648;
static constexpr int LROW  = 36864;   // 128 inv-l
static constexpr int MBITS = 36992;   // 4 u32
static constexpr int SMEMF = 37000;
static constexpr int SMEM_BYTES = SMEMF * 4;   // ~144.5 KB -> 1 CTA/SM

__device__ __forceinline__ uint32_t f2tf(float x) {
    uint32_t r;
    asm("cvt.rna.tf32.f32 %0, %1;" : "=r"(r) : "f"(x));
    return r;
}

__device__ __forceinline__ void mma8(float* d, const uint32_t* a, uint32_t b0, uint32_t b1) {
    asm volatile(
        "mma.sync.aligned.m16n8k8.row.col.f32.tf32.tf32.f32 "
        "{%0,%1,%2,%3}, {%4,%5,%6,%7}, {%8,%9}, {%0,%1,%2,%3};"
        : "+f"(d[0]), "+f"(d[1]), "+f"(d[2]), "+f"(d[3])
        : "r"(a[0]), "r"(a[1]), "r"(a[2]), "r"(a[3]), "r"(b0), "r"(b1));
}

__device__ __forceinline__ uint32_t s2u(const void* p) {
    uint32_t a;
    asm("{ .reg .u64 t; cvta.to.shared.u64 t, %1; cvt.u32.u64 %0, t; }" : "=r"(a) : "l"(p));
    return a;
}

__device__ __forceinline__ void cpa16(uint32_t dst, const float* src) {
    asm volatile("cp.async.cg.shared.global [%0], [%1], 16;" :: "r"(dst), "l"(src));
}

extern __shared__ float smf[];

// stage one 128x64 K tile + one 128x64 V tile, raw rows, stride 72
__device__ __forceinline__ void stage_kv(uint32_t sk, uint32_t sv,
                                         const float* __restrict__ kg,
                                         const float* __restrict__ vg, int tid) {
    #pragma unroll
    for (int it = 0; it < 8; it++) {
        int i4 = (tid + it * 256) * 4;
        int s = i4 >> 6, h0 = i4 & 63;
        uint32_t off = (uint32_t)(s * 72 + h0) * 4u;
        cpa16(sk + off, kg + i4);
        cpa16(sv + off, vg + i4);
    }
}

__global__ void __launch_bounds__(NT, 1)
attn_fused(const float* __restrict__ q, const float* __restrict__ k,
           const float* __restrict__ v, const int* __restrict__ mask,
           float* __restrict__ out)
{
    const int tid = threadIdx.x;
    const int w = tid >> 5, lane = tid & 31;
    const int rw = lane >> 2, tm = lane & 3;
    const int bx = blockIdx.x;
    const int b = bx >> 4, t0 = (bx & 15) << 7;

    const float* qb = q + ((size_t)b * T_ + t0) * H_;
    const float* kb = k + (size_t)b * S_ * H_;
    const float* vb = v + (size_t)b * S_ * H_;
    const int*   mb = mask + (size_t)b * S_;
    float* pp = out + (size_t)B_ * T_ * H_ + ((size_t)b * T_ + t0) * S_;
    float* oo = out + ((size_t)b * T_ + t0) * H_;

    const uint32_t sb = s2u(smf);
    uint32_t* mbu = (uint32_t*)(smf + MBITS);
    const int prow = 16 * w + rw;

    // prefetch tile 0
    stage_kv(sb + KBUF0 * 4, sb + VBUF0 * 4, kb, vb, tid);
    asm volatile("cp.async.commit_group;" ::: "memory");

    // ---- Q fragments, pre-split hi/lo, resident in registers ----
    uint32_t ah[8][4], al[8][4];
    #pragma unroll
    for (int ks = 0; ks < 8; ks++) {
        const int c = ks * 8 + tm;
        float x0 = qb[prow * 64 + c];
        float x1 = qb[(prow + 8) * 64 + c];
        float x2 = qb[prow * 64 + c + 4];
        float x3 = qb[(prow + 8) * 64 + c + 4];
        ah[ks][0] = f2tf(x0); al[ks][0] = __float_as_uint(x0 - __uint_as_float(ah[ks][0]));
        ah[ks][1] = f2tf(x1); al[ks][1] = __float_as_uint(x1 - __uint_as_float(ah[ks][1]));
        ah[ks][2] = f2tf(x2); al[ks][2] = __float_as_uint(x2 - __uint_as_float(ah[ks][2]));
        ah[ks][3] = f2tf(x3); al[ks][3] = __float_as_uint(x3 - __uint_as_float(ah[ks][3]));
    }

    float O[8][4];
    #pragma unroll
    for (int i = 0; i < 8; i++)
        #pragma unroll
        for (int jj = 0; jj < 4; jj++) O[i][jj] = 0.0f;
    float lac0 = 0.0f, lac1 = 0.0f;

    const int srcA = (lane & ~3) | (tm >> 1);
    const int srcB = srcA + 2;
    const bool odd = (tm & 1) != 0;

    for (int j = 0; j < 16; j++) {
        const int s0 = j << 7;
        const float* Ks = smf + ((j & 1) ? KBUF1 : KBUF0);
        const float* Vs = smf + ((j & 1) ? VBUF1 : VBUF0);

        // prefetch next tile into the buffer freed by tile j-1 (sync at prev loop end)
        if (j < 15) {
            uint32_t nk = sb + ((j & 1) ? KBUF0 : KBUF1) * 4;
            uint32_t nv = sb + ((j & 1) ? VBUF0 : VBUF1) * 4;
            stage_kv(nk, nv, kb + (size_t)(s0 + 128) * H_, vb + (size_t)(s0 + 128) * H_, tid);
            asm volatile("cp.async.commit_group;" ::: "memory");
        }
        // mask bits for tile j
        if (tid < 128) {
            unsigned mv = __ballot_sync(0xffffffffu, mb[s0 + tid] != 0);
            if (lane == 0) mbu[w] = mv;
        }
        if (j < 15) asm volatile("cp.async.wait_group 1;" ::: "memory");
        else        asm volatile("cp.async.wait_group 0;" ::: "memory");
        __syncthreads();

        #pragma unroll 2
        for (int nt = 0; nt < 16; nt++) {
            // ---- QK^T for this 8-col strip: 3 independent accumulation chains ----
            float dh[4] = {0.f,0.f,0.f,0.f}, dm[4] = {0.f,0.f,0.f,0.f}, dl[4] = {0.f,0.f,0.f,0.f};
            const int nrow = nt * 8 + rw;
            #pragma unroll
            for (int ks = 0; ks < 8; ks++) {
                float k0 = Ks[nrow * 72 + ks * 8 + tm];
                float k1 = Ks[nrow * 72 + ks * 8 + tm + 4];
                uint32_t bh0 = f2tf(k0), bh1 = f2tf(k1);
                uint32_t bl0 = __float_as_uint(k0 - __uint_as_float(bh0));
                uint32_t bl1 = __float_as_uint(k1 - __uint_as_float(bh1));
                mma8(dh, ah[ks], bh0, bh1);
                mma8(dm, al[ks], bh0, bh1);
                mma8(dl, ah[ks], bl0, bl1);
            }
            // ---- mask + exp (no-max softmax: s ~ N(0,64), exp can't overflow fp32) ----
            uint32_t wb = mbu[nt >> 2];
            int sh = ((nt & 3) << 3) + 2 * tm;
            float e0 = ((wb >> sh) & 1u)       ? __expf(dh[0] + dm[0] + dl[0]) : 0.0f;
            float e1 = ((wb >> (sh + 1)) & 1u) ? __expf(dh[1] + dm[1] + dl[1]) : 0.0f;
            float e2 = ((wb >> sh) & 1u)       ? __expf(dh[2] + dm[2] + dl[2]) : 0.0f;
            float e3 = ((wb >> (sh + 1)) & 1u) ? __expf(dh[3] + dm[3] + dl[3]) : 0.0f;
            lac0 += e0 + e1;
            lac1 += e2 + e3;
            const int cg = nt * 8 + 2 * tm;
            __stcs((float2*)(pp + (size_t)prow * S_ + s0 + cg), make_float2(e0, e1));
            __stcs((float2*)(pp + (size_t)(prow + 8) * S_ + s0 + cg), make_float2(e2, e3));

            // ---- C-frag -> A-frag via quad butterfly (cols {2t,2t+1} -> {t,t+4}) ----
            float x, y;
            x = __shfl_sync(0xffffffffu, e0, srcA); y = __shfl_sync(0xffffffffu, e1, srcA);
            float a0 = odd ? y : x;
            x = __shfl_sync(0xffffffffu, e0, srcB); y = __shfl_sync(0xffffffffu, e1, srcB);
            float a2 = odd ? y : x;
            x = __shfl_sync(0xffffffffu, e2, srcA); y = __shfl_sync(0xffffffffu, e3, srcA);
            float a1 = odd ? y : x;
            x = __shfl_sync(0xffffffffu, e2, srcB); y = __shfl_sync(0xffffffffu, e3, srcB);
            float a3 = odd ? y : x;

            uint32_t pah[4], pal[4];
            pah[0] = f2tf(a0); pal[0] = __float_as_uint(a0 - __uint_as_float(pah[0]));
            pah[1] = f2tf(a1); pal[1] = __float_as_uint(a1 - __uint_as_float(pah[1]));
            pah[2] = f2tf(a2); pal[2] = __float_as_uint(a2 - __uint_as_float(pah[2]));
            pah[3] = f2tf(a3); pal[3] = __float_as_uint(a3 - __uint_as_float(pah[3]));

            // ---- PV for this k-strip: 8 independent O chains ----
            #pragma unroll
            for (int vt = 0; vt < 8; vt++) {
                float v0 = Vs[(nt * 8 + tm) * 72 + vt * 8 + rw];
                float v1 = Vs[(nt * 8 + tm + 4) * 72 + vt * 8 + rw];
                uint32_t vh0 = f2tf(v0), vh1 = f2tf(v1);
                uint32_t vl0 = __float_as_uint(v0 - __uint_as_float(vh0));
                uint32_t vl1 = __float_as_uint(v1 - __uint_as_float(vh1));
                mma8(O[vt], pah, vh0, vh1);
                mma8(O[vt], pal, vh0, vh1);
                mma8(O[vt], pah, vl0, vl1);
            }
        }
        __syncthreads();   // all reads of this buffer done before next prefetch overwrites
    }

    // ---- reduce l across the 4 lanes of each row quad, store 1/l ----
    lac0 += __shfl_xor_sync(0xffffffffu, lac0, 1);
    lac0 += __shfl_xor_sync(0xffffffffu, lac0, 2);
    lac1 += __shfl_xor_sync(0xffffffffu, lac1, 1);
    lac1 += __shfl_xor_sync(0xffffffffu, lac1, 2);
    if (tm == 0) {
        smf[LROW + prow]     = 1.0f / lac0;
        smf[LROW + prow + 8] = 1.0f / lac1;
    }
    __syncthreads();
    const float il0 = smf[LROW + prow];
    const float il1 = smf[LROW + prow + 8];

    // ---- write O (normalized) ----
    #pragma unroll
    for (int vt = 0; vt < 8; vt++) {
        int c = vt * 8 + 2 * tm;
        *(float2*)(oo + (size_t)prow * H_ + c)       = make_float2(O[vt][0] * il0, O[vt][1] * il0);
        *(float2*)(oo + (size_t)(prow + 8) * H_ + c) = make_float2(O[vt][2] * il1, O[vt][3] * il1);
    }

    // ---- rescale p: coalesced sweep over this CTA's 128x2048 slice ----
    for (int i = tid; i < 128 * 512; i += NT) {
        int row = i >> 9, c4 = i & 511;
        float il = smf[LROW + row];
        float4* g = (float4*)(pp + (size_t)row * S_) + c4;
        float4 vv = __ldcs(g);
        vv.x *= il; vv.y *= il; vv.z *= il; vv.w *= il;
        __stcs(g, vv);
    }
}

extern "C" void kernel_launch(void* const* d_in, const int* in_sizes, int n_in,
                              void* d_out, int out_size)
{
    const float* q    = (const float*)d_in[0];
    const float* keys = (const float*)d_in[1];
    const float* vals = (const float*)d_in[2];
    const int*   mask = (const int*)d_in[3];
    float* out = (float*)d_out;

    cudaFuncSetAttribute(attn_fused, cudaFuncAttributeMaxDynamicSharedMemorySize, SMEM_BYTES);
    attn_fused<<<B_ * (T_ / 128), NT, SMEM_BYTES>>>(q, keys, vals, mask, out);
}

// round 7
// speedup vs baseline: 1.2710x; 1.2710x over previous
#include <cuda_runtime.h>
#include <cuda_fp16.h>
#include <cstdint>

static constexpr int B_ = 8, T_ = 2048, S_ = 2048, H_ = 64;
static constexpr int NT = 256;

// smem u32-unit offsets
static constexpr int KHI = 0;        // K hi: [s:128][kpair:32] stride 36
static constexpr int KLO = 4608;
static constexpr int VHI = 9216;     // V hi: [h:64][spair:64] stride 68
static constexpr int VLO = 13568;
static constexpr int LROWU  = 17920; // 128 floats: per-row p-normalizer 1/(lm*exp(m))
static constexpr int MBITSU = 18048; // 4 u32 mask bits
static constexpr int SMEMU  = 18052;
static constexpr int SMEM_BYTES = SMEMU * 4;   // ~72 KB

__device__ __forceinline__ void mma16(float* d, const uint32_t* a, uint32_t b0, uint32_t b1) {
    asm volatile(
        "mma.sync.aligned.m16n8k16.row.col.f32.f16.f16.f32 "
        "{%0,%1,%2,%3}, {%4,%5,%6,%7}, {%8,%9}, {%0,%1,%2,%3};"
        : "+f"(d[0]), "+f"(d[1]), "+f"(d[2]), "+f"(d[3])
        : "r"(a[0]), "r"(a[1]), "r"(a[2]), "r"(a[3]), "r"(b0), "r"(b1));
}

// split (x,y) into packed fp16 hi pair (returned) and lo-residual pair (out param)
__device__ __forceinline__ uint32_t packhl(float x, float y, uint32_t& lo) {
    __half hx = __float2half_rn(x), hy = __float2half_rn(y);
    __half2 L = __floats2half2_rn(x - __half2float(hx), y - __half2float(hy));
    __half2 Hh = __halves2half2(hx, hy);
    lo = *(uint32_t*)&L;
    return *(uint32_t*)&Hh;
}

extern __shared__ uint32_t smu[];

__global__ void __launch_bounds__(NT, 1)
attn_h2(const float* __restrict__ q, const float* __restrict__ k,
        const float* __restrict__ v, const int* __restrict__ mask,
        float* __restrict__ out)
{
    const int tid = threadIdx.x;
    const int w = tid >> 5, lane = tid & 31;
    const int n_ = lane >> 2, tm = lane & 3;
    const int bx = blockIdx.x;
    const int b = bx >> 4, t0 = (bx & 15) << 7;

    const float* qb = q + ((size_t)b * T_ + t0) * H_;
    const float* kb = k + (size_t)b * S_ * H_;
    const float* vb = v + (size_t)b * S_ * H_;
    const int*   mb = mask + (size_t)b * S_;
    float* pp = out + (size_t)B_ * T_ * H_ + ((size_t)b * T_ + t0) * S_;
    float* oo = out + ((size_t)b * T_ + t0) * H_;

    float* smf = (float*)smu;
    const int prow = 16 * w + n_;

    // ---- Q fragments: 4 k16-chunks, pre-split fp16 hi/lo, in registers ----
    uint32_t qh[4][4], ql[4][4];
    #pragma unroll
    for (int kc = 0; kc < 4; kc++) {
        const int base = kc * 16 + 2 * tm;
        float2 x0 = *(const float2*)(qb + prow * 64 + base);
        float2 x1 = *(const float2*)(qb + (prow + 8) * 64 + base);
        float2 x2 = *(const float2*)(qb + prow * 64 + base + 8);
        float2 x3 = *(const float2*)(qb + (prow + 8) * 64 + base + 8);
        qh[kc][0] = packhl(x0.x, x0.y, ql[kc][0]);
        qh[kc][1] = packhl(x1.x, x1.y, ql[kc][1]);
        qh[kc][2] = packhl(x2.x, x2.y, ql[kc][2]);
        qh[kc][3] = packhl(x3.x, x3.y, ql[kc][3]);
    }

    float O[8][4];
    #pragma unroll
    for (int i = 0; i < 8; i++)
        #pragma unroll
        for (int jj = 0; jj < 4; jj++) O[i][jj] = 0.0f;
    // flash-style per-row state (rows prow and prow+8)
    float m0 = -3.0e38f, m1 = -3.0e38f, lm0 = 0.0f, lm1 = 0.0f;

    const int ks_s  = tid >> 4;          // K staging: s row (+16 per it)
    const int ks_k4 = (tid & 15) * 4;    // first of 4 k values
    const int vs_sp = tid & 63;          // V staging: s-pair
    const int vs_h0 = (tid >> 6) * 16;   // h block of 16

    for (int j = 0; j < 16; j++) {
        const int s0 = j << 7;
        __syncthreads();   // previous tile's reads complete

        // ---- stage K: hi/lo fp16 pairs, [s][kpair] stride 36 ----
        const float* kt = kb + (size_t)s0 * H_;
        #pragma unroll
        for (int it = 0; it < 8; it++) {
            int s = ks_s + it * 16;
            float4 x = *(const float4*)(kt + s * 64 + ks_k4);
            uint32_t l0, l1;
            uint32_t h0 = packhl(x.x, x.y, l0);
            uint32_t h1 = packhl(x.z, x.w, l1);
            *(uint2*)&smu[KHI + s * 36 + (ks_k4 >> 1)] = make_uint2(h0, h1);
            *(uint2*)&smu[KLO + s * 36 + (ks_k4 >> 1)] = make_uint2(l0, l1);
        }
        // ---- stage V: pairs (V[2sp][h], V[2sp+1][h]) at [h][sp] stride 68 ----
        {
            const float* r0 = vb + (size_t)(s0 + 2 * vs_sp) * H_ + vs_h0;
            const float* r1 = r0 + H_;
            #pragma unroll
            for (int i = 0; i < 4; i++) {
                float4 a = *(const float4*)(r0 + i * 4);
                float4 c = *(const float4*)(r1 + i * 4);
                uint32_t lo;
                int hh = vs_h0 + i * 4;
                uint32_t hi0 = packhl(a.x, c.x, lo);
                smu[VHI + (hh + 0) * 68 + vs_sp] = hi0; smu[VLO + (hh + 0) * 68 + vs_sp] = lo;
                uint32_t hi1 = packhl(a.y, c.y, lo);
                smu[VHI + (hh + 1) * 68 + vs_sp] = hi1; smu[VLO + (hh + 1) * 68 + vs_sp] = lo;
                uint32_t hi2 = packhl(a.z, c.z, lo);
                smu[VHI + (hh + 2) * 68 + vs_sp] = hi2; smu[VLO + (hh + 2) * 68 + vs_sp] = lo;
                uint32_t hi3 = packhl(a.w, c.w, lo);
                smu[VHI + (hh + 3) * 68 + vs_sp] = hi3; smu[VLO + (hh + 3) * 68 + vs_sp] = lo;
            }
        }
        if (tid < 128) {
            unsigned mv = __ballot_sync(0xffffffffu, mb[s0 + tid] != 0);
            if (lane == 0) smu[MBITSU + w] = mv;
        }
        __syncthreads();

        const uint32_t* Kh = smu + KHI;
        const uint32_t* Kl = smu + KLO;
        const uint32_t* Vh = smu + VHI;
        const uint32_t* Vl = smu + VLO;

        #pragma unroll 2
        for (int ntp = 0; ntp < 8; ntp++) {
            float sv[2][4];
            uint32_t bt[2][2];   // per-strip mask bits for the 2 cols
            // ---- raw QK^T scores for the two 8-col strips ----
            #pragma unroll
            for (int si = 0; si < 2; si++) {
                const int strip = ntp * 2 + si;
                float dh[4] = {0.f,0.f,0.f,0.f}, dm[4] = {0.f,0.f,0.f,0.f}, dl[4] = {0.f,0.f,0.f,0.f};
                const int kb0 = (strip * 8 + n_) * 36 + tm;
                #pragma unroll
                for (int kc = 0; kc < 4; kc++) {
                    uint32_t bh0 = Kh[kb0 + kc * 8], bh1 = Kh[kb0 + kc * 8 + 4];
                    uint32_t bl0 = Kl[kb0 + kc * 8], bl1 = Kl[kb0 + kc * 8 + 4];
                    mma16(dh, qh[kc], bh0, bh1);
                    mma16(dm, ql[kc], bh0, bh1);
                    mma16(dl, qh[kc], bl0, bl1);
                }
                #pragma unroll
                for (int x = 0; x < 4; x++) sv[si][x] = dh[x] + dm[x] + dl[x];
                uint32_t wb = smu[MBITSU + (strip >> 2)];
                int sh = ((strip & 3) << 3) + 2 * tm;
                bt[si][0] = (wb >> sh) & 1u;
                bt[si][1] = (wb >> (sh + 1)) & 1u;
            }
            // ---- mask-aware running max update (rows prow, prow+8) ----
            float t0 = -3.0e38f, t1 = -3.0e38f;
            #pragma unroll
            for (int si = 0; si < 2; si++) {
                if (bt[si][0]) { t0 = fmaxf(t0, sv[si][0]); t1 = fmaxf(t1, sv[si][2]); }
                if (bt[si][1]) { t0 = fmaxf(t0, sv[si][1]); t1 = fmaxf(t1, sv[si][3]); }
            }
            t0 = fmaxf(t0, __shfl_xor_sync(0xffffffffu, t0, 1));
            t0 = fmaxf(t0, __shfl_xor_sync(0xffffffffu, t0, 2));
            t1 = fmaxf(t1, __shfl_xor_sync(0xffffffffu, t1, 1));
            t1 = fmaxf(t1, __shfl_xor_sync(0xffffffffu, t1, 2));
            float m0n = fmaxf(m0, t0), m1n = fmaxf(m1, t1);
            float f0 = __expf(m0 - m0n), f1 = __expf(m1 - m1n);
            lm0 *= f0; lm1 *= f1;
            #pragma unroll
            for (int vt = 0; vt < 8; vt++) {
                O[vt][0] *= f0; O[vt][1] *= f0;
                O[vt][2] *= f1; O[vt][3] *= f1;
            }
            m0 = m0n; m1 = m1n;
            const float expm0 = __expf(m0), expm1 = __expf(m1);

            // ---- exp (bounded <=1), p raw store, pack fp16 A-frags ----
            float e[2][4];
            #pragma unroll
            for (int si = 0; si < 2; si++) {
                e[si][0] = bt[si][0] ? __expf(sv[si][0] - m0) : 0.0f;
                e[si][1] = bt[si][1] ? __expf(sv[si][1] - m0) : 0.0f;
                e[si][2] = bt[si][0] ? __expf(sv[si][2] - m1) : 0.0f;
                e[si][3] = bt[si][1] ? __expf(sv[si][3] - m1) : 0.0f;
                lm0 += e[si][0] + e[si][1];
                lm1 += e[si][2] + e[si][3];
                const int cg = (ntp * 2 + si) * 8 + 2 * tm;
                __stcs((float2*)(pp + (size_t)prow * S_ + s0 + cg),
                       make_float2(e[si][0] * expm0, e[si][1] * expm0));
                __stcs((float2*)(pp + (size_t)(prow + 8) * S_ + s0 + cg),
                       make_float2(e[si][2] * expm1, e[si][3] * expm1));
            }
            uint32_t pah[4], pal[4];
            pah[0] = packhl(e[0][0], e[0][1], pal[0]);
            pah[1] = packhl(e[0][2], e[0][3], pal[1]);
            pah[2] = packhl(e[1][0], e[1][1], pal[2]);
            pah[3] = packhl(e[1][2], e[1][3], pal[3]);

            // ---- PV: k16 chunk = this strip pair; 8 independent O chains ----
            const int vb0 = ntp * 8 + tm;
            #pragma unroll
            for (int vt = 0; vt < 8; vt++) {
                const int a0 = (vt * 8 + n_) * 68 + vb0;
                uint32_t vh0_ = Vh[a0], vh1_ = Vh[a0 + 4];
                uint32_t vl0_ = Vl[a0], vl1_ = Vl[a0 + 4];
                mma16(O[vt], pah, vh0_, vh1_);
                mma16(O[vt], pal, vh0_, vh1_);
                mma16(O[vt], pah, vl0_, vl1_);
            }
        }
    }

    // ---- quad-reduce lm; O normalizer and p-row normalizer ----
    lm0 += __shfl_xor_sync(0xffffffffu, lm0, 1);
    lm0 += __shfl_xor_sync(0xffffffffu, lm0, 2);
    lm1 += __shfl_xor_sync(0xffffffffu, lm1, 1);
    lm1 += __shfl_xor_sync(0xffffffffu, lm1, 2);
    const float iv0 = 1.0f / lm0;
    const float iv1 = 1.0f / lm1;
    __syncthreads();
    if (tm == 0) {
        smf[LROWU + prow]     = iv0 / __expf(m0);   // 1 / (lm * exp(m))
        smf[LROWU + prow + 8] = iv1 / __expf(m1);
    }
    __syncthreads();

    // ---- write O (normalized) ----
    #pragma unroll
    for (int vt = 0; vt < 8; vt++) {
        int c = vt * 8 + 2 * tm;
        *(float2*)(oo + (size_t)prow * H_ + c)       = make_float2(O[vt][0] * iv0, O[vt][1] * iv0);
        *(float2*)(oo + (size_t)(prow + 8) * H_ + c) = make_float2(O[vt][2] * iv1, O[vt][3] * iv1);
    }

    // ---- rescale p: coalesced sweep over this CTA's 128x2048 slice ----
    for (int i = tid; i < 128 * 512; i += NT) {
        int row = i >> 9, c4 = i & 511;
        float il = smf[LROWU + row];
        float4* g = (float4*)(pp + (size_t)row * S_) + c4;
        float4 vv = __ldcs(g);
        vv.x *= il; vv.y *= il; vv.z *= il; vv.w *= il;
        __stcs(g, vv);
    }
}

extern "C" void kernel_launch(void* const* d_in, const int* in_sizes, int n_in,
                              void* d_out, int out_size)
{
    const float* q    = (const float*)d_in[0];
    const float* keys = (const float*)d_in[1];
    const float* vals = (const float*)d_in[2];
    const int*   mask = (const int*)d_in[3];
    float* out = (float*)d_out;

    cudaFuncSetAttribute(attn_h2, cudaFuncAttributeMaxDynamicSharedMemorySize, SMEM_BYTES);
    attn_h2<<<B_ * (T_ / 128), NT, SMEM_BYTES>>>(q, keys, vals, mask, out);
}

// round 8
// speedup vs baseline: 1.2777x; 1.0053x over previous
#include <cuda_runtime.h>
#include <cuda_fp16.h>
#include <cstdint>

static constexpr int B_ = 8, T_ = 2048, S_ = 2048, H_ = 64;
static constexpr int NT = 256;

// smem u32-unit offsets
static constexpr int KHI = 0;        // K hi: [s:128][kpair:32] stride 36
static constexpr int KLO = 4608;
static constexpr int VHI = 9216;     // V hi: [h:64][spair:64] stride 68
static constexpr int VLO = 13568;
static constexpr int LROWU  = 17920; // 128 floats: per-row p-normalizer 1/(lm*exp(m))
static constexpr int MBITSU = 18048; // 4 u32 mask bits
static constexpr int SMEMU  = 18052;
static constexpr int SMEM_BYTES = SMEMU * 4;   // ~72 KB

__device__ __forceinline__ void mma16(float* d, const uint32_t* a, uint32_t b0, uint32_t b1) {
    asm volatile(
        "mma.sync.aligned.m16n8k16.row.col.f32.f16.f16.f32 "
        "{%0,%1,%2,%3}, {%4,%5,%6,%7}, {%8,%9}, {%0,%1,%2,%3};"
        : "+f"(d[0]), "+f"(d[1]), "+f"(d[2]), "+f"(d[3])
        : "r"(a[0]), "r"(a[1]), "r"(a[2]), "r"(a[3]), "r"(b0), "r"(b1));
}

// split (x,y) into packed fp16 hi pair (returned) and lo-residual pair (out param)
__device__ __forceinline__ uint32_t packhl(float x, float y, uint32_t& lo) {
    __half hx = __float2half_rn(x), hy = __float2half_rn(y);
    __half2 L = __floats2half2_rn(x - __half2float(hx), y - __half2float(hy));
    __half2 Hh = __halves2half2(hx, hy);
    lo = *(uint32_t*)&L;
    return *(uint32_t*)&Hh;
}

extern __shared__ uint32_t smu[];

__global__ void __launch_bounds__(NT, 1)
attn_h2(const float* __restrict__ q, const float* __restrict__ k,
        const float* __restrict__ v, const int* __restrict__ mask,
        float* __restrict__ out)
{
    const int tid = threadIdx.x;
    const int w = tid >> 5, lane = tid & 31;
    const int n_ = lane >> 2, tm = lane & 3;
    const int bx = blockIdx.x;
    const int b = bx >> 4, t0 = (bx & 15) << 7;

    const float* qb = q + ((size_t)b * T_ + t0) * H_;
    const float* kb = k + (size_t)b * S_ * H_;
    const float* vb = v + (size_t)b * S_ * H_;
    const int*   mb = mask + (size_t)b * S_;
    float* pp = out + (size_t)B_ * T_ * H_ + ((size_t)b * T_ + t0) * S_;
    float* oo = out + ((size_t)b * T_ + t0) * H_;

    float* smf = (float*)smu;
    const int prow = 16 * w + n_;

    // ---- Q fragments: 4 k16-chunks, pre-split fp16 hi/lo, in registers ----
    uint32_t qh[4][4], ql[4][4];
    #pragma unroll
    for (int kc = 0; kc < 4; kc++) {
        const int base = kc * 16 + 2 * tm;
        float2 x0 = *(const float2*)(qb + prow * 64 + base);
        float2 x1 = *(const float2*)(qb + (prow + 8) * 64 + base);
        float2 x2 = *(const float2*)(qb + prow * 64 + base + 8);
        float2 x3 = *(const float2*)(qb + (prow + 8) * 64 + base + 8);
        qh[kc][0] = packhl(x0.x, x0.y, ql[kc][0]);
        qh[kc][1] = packhl(x1.x, x1.y, ql[kc][1]);
        qh[kc][2] = packhl(x2.x, x2.y, ql[kc][2]);
        qh[kc][3] = packhl(x3.x, x3.y, ql[kc][3]);
    }

    float O[8][4];
    #pragma unroll
    for (int i = 0; i < 8; i++)
        #pragma unroll
        for (int jj = 0; jj < 4; jj++) O[i][jj] = 0.0f;
    // flash state per row-pair; em = exp(m) cached, refreshed only on (rare) max bumps
    float m0 = -3.0e38f, m1 = -3.0e38f, lm0 = 0.0f, lm1 = 0.0f;
    float em0 = 0.0f, em1 = 0.0f;
    const float LOGT = 10.0f;   // common-path bound: e <= exp(10) ~ 22026 << 65504 (fp16 max)

    const int ks_s  = tid >> 4;          // K staging: s row (+16 per it)
    const int ks_k4 = (tid & 15) * 4;    // first of 4 k values
    const int vs_sp = tid & 63;          // V staging: s-pair
    const int vs_h0 = (tid >> 6) * 16;   // h block of 16

    for (int j = 0; j < 16; j++) {
        const int s0 = j << 7;
        __syncthreads();   // previous tile's reads complete

        // ---- stage K: hi/lo fp16 pairs, [s][kpair] stride 36 ----
        const float* kt = kb + (size_t)s0 * H_;
        #pragma unroll
        for (int it = 0; it < 8; it++) {
            int s = ks_s + it * 16;
            float4 x = *(const float4*)(kt + s * 64 + ks_k4);
            uint32_t l0, l1;
            uint32_t h0 = packhl(x.x, x.y, l0);
            uint32_t h1 = packhl(x.z, x.w, l1);
            *(uint2*)&smu[KHI + s * 36 + (ks_k4 >> 1)] = make_uint2(h0, h1);
            *(uint2*)&smu[KLO + s * 36 + (ks_k4 >> 1)] = make_uint2(l0, l1);
        }
        // ---- stage V: pairs (V[2sp][h], V[2sp+1][h]) at [h][sp] stride 68 ----
        {
            const float* r0 = vb + (size_t)(s0 + 2 * vs_sp) * H_ + vs_h0;
            const float* r1 = r0 + H_;
            #pragma unroll
            for (int i = 0; i < 4; i++) {
                float4 a = *(const float4*)(r0 + i * 4);
                float4 c = *(const float4*)(r1 + i * 4);
                uint32_t lo;
                int hh = vs_h0 + i * 4;
                uint32_t hi0 = packhl(a.x, c.x, lo);
                smu[VHI + (hh + 0) * 68 + vs_sp] = hi0; smu[VLO + (hh + 0) * 68 + vs_sp] = lo;
                uint32_t hi1 = packhl(a.y, c.y, lo);
                smu[VHI + (hh + 1) * 68 + vs_sp] = hi1; smu[VLO + (hh + 1) * 68 + vs_sp] = lo;
                uint32_t hi2 = packhl(a.z, c.z, lo);
                smu[VHI + (hh + 2) * 68 + vs_sp] = hi2; smu[VLO + (hh + 2) * 68 + vs_sp] = lo;
                uint32_t hi3 = packhl(a.w, c.w, lo);
                smu[VHI + (hh + 3) * 68 + vs_sp] = hi3; smu[VLO + (hh + 3) * 68 + vs_sp] = lo;
            }
        }
        if (tid < 128) {
            unsigned mv = __ballot_sync(0xffffffffu, mb[s0 + tid] != 0);
            if (lane == 0) smu[MBITSU + w] = mv;
        }
        __syncthreads();

        const uint32_t* Kh = smu + KHI;
        const uint32_t* Kl = smu + KLO;
        const uint32_t* Vh = smu + VHI;
        const uint32_t* Vl = smu + VLO;

        #pragma unroll 2
        for (int ntp = 0; ntp < 8; ntp++) {
            float sv[2][4];
            uint32_t bt[2][2];   // per-strip mask bits for the 2 cols
            // ---- raw QK^T scores for the two 8-col strips ----
            #pragma unroll
            for (int si = 0; si < 2; si++) {
                const int strip = ntp * 2 + si;
                float dh[4] = {0.f,0.f,0.f,0.f}, dm[4] = {0.f,0.f,0.f,0.f}, dl[4] = {0.f,0.f,0.f,0.f};
                const int kb0 = (strip * 8 + n_) * 36 + tm;
                #pragma unroll
                for (int kc = 0; kc < 4; kc++) {
                    uint32_t bh0 = Kh[kb0 + kc * 8], bh1 = Kh[kb0 + kc * 8 + 4];
                    uint32_t bl0 = Kl[kb0 + kc * 8], bl1 = Kl[kb0 + kc * 8 + 4];
                    mma16(dh, qh[kc], bh0, bh1);
                    mma16(dm, ql[kc], bh0, bh1);
                    mma16(dl, qh[kc], bl0, bl1);
                }
                #pragma unroll
                for (int x = 0; x < 4; x++) sv[si][x] = dh[x] + dm[x] + dl[x];
                uint32_t wb = smu[MBITSU + (strip >> 2)];
                int sh = ((strip & 3) << 3) + 2 * tm;
                bt[si][0] = (wb >> sh) & 1u;
                bt[si][1] = (wb >> (sh + 1)) & 1u;
            }
            // ---- per-lane masked max for the overflow check ----
            float t0 = -3.0e38f, t1 = -3.0e38f;
            #pragma unroll
            for (int si = 0; si < 2; si++) {
                if (bt[si][0]) { t0 = fmaxf(t0, sv[si][0]); t1 = fmaxf(t1, sv[si][2]); }
                if (bt[si][1]) { t0 = fmaxf(t0, sv[si][1]); t1 = fmaxf(t1, sv[si][3]); }
            }
            // ---- lazy max: exact slow path only if e would leave fp16-safe range ----
            bool big = (t0 > m0 + LOGT) || (t1 > m1 + LOGT);
            if (__any_sync(0xffffffffu, big)) {
                t0 = fmaxf(t0, __shfl_xor_sync(0xffffffffu, t0, 1));
                t0 = fmaxf(t0, __shfl_xor_sync(0xffffffffu, t0, 2));
                t1 = fmaxf(t1, __shfl_xor_sync(0xffffffffu, t1, 1));
                t1 = fmaxf(t1, __shfl_xor_sync(0xffffffffu, t1, 2));
                float m0n = fmaxf(m0, t0), m1n = fmaxf(m1, t1);
                float f0 = __expf(m0 - m0n), f1 = __expf(m1 - m1n);
                lm0 *= f0; lm1 *= f1;
                #pragma unroll
                for (int vt = 0; vt < 8; vt++) {
                    O[vt][0] *= f0; O[vt][1] *= f0;
                    O[vt][2] *= f1; O[vt][3] *= f1;
                }
                m0 = m0n; m1 = m1n;
                em0 = __expf(m0); em1 = __expf(m1);
            }

            // ---- exp (bounded <= exp(LOGT)), p raw store, pack fp16 A-frags ----
            float e[2][4];
            #pragma unroll
            for (int si = 0; si < 2; si++) {
                e[si][0] = bt[si][0] ? __expf(sv[si][0] - m0) : 0.0f;
                e[si][1] = bt[si][1] ? __expf(sv[si][1] - m0) : 0.0f;
                e[si][2] = bt[si][0] ? __expf(sv[si][2] - m1) : 0.0f;
                e[si][3] = bt[si][1] ? __expf(sv[si][3] - m1) : 0.0f;
                lm0 += e[si][0] + e[si][1];
                lm1 += e[si][2] + e[si][3];
                const int cg = (ntp * 2 + si) * 8 + 2 * tm;
                __stcs((float2*)(pp + (size_t)prow * S_ + s0 + cg),
                       make_float2(e[si][0] * em0, e[si][1] * em0));
                __stcs((float2*)(pp + (size_t)(prow + 8) * S_ + s0 + cg),
                       make_float2(e[si][2] * em1, e[si][3] * em1));
            }
            uint32_t pah[4], pal[4];
            pah[0] = packhl(e[0][0], e[0][1], pal[0]);
            pah[1] = packhl(e[0][2], e[0][3], pal[1]);
            pah[2] = packhl(e[1][0], e[1][1], pal[2]);
            pah[3] = packhl(e[1][2], e[1][3], pal[3]);

            // ---- PV: k16 chunk = this strip pair; 8 independent O chains ----
            const int vb0 = ntp * 8 + tm;
            #pragma unroll
            for (int vt = 0; vt < 8; vt++) {
                const int a0 = (vt * 8 + n_) * 68 + vb0;
                uint32_t vh0_ = Vh[a0], vh1_ = Vh[a0 + 4];
                uint32_t vl0_ = Vl[a0], vl1_ = Vl[a0 + 4];
                mma16(O[vt], pah, vh0_, vh1_);
                mma16(O[vt], pal, vh0_, vh1_);
                mma16(O[vt], pah, vl0_, vl1_);
            }
        }
    }

    // ---- quad-reduce lm; O normalizer and p-row normalizer ----
    lm0 += __shfl_xor_sync(0xffffffffu, lm0, 1);
    lm0 += __shfl_xor_sync(0xffffffffu, lm0, 2);
    lm1 += __shfl_xor_sync(0xffffffffu, lm1, 1);
    lm1 += __shfl_xor_sync(0xffffffffu, lm1, 2);
    const float iv0 = 1.0f / lm0;
    const float iv1 = 1.0f / lm1;
    __syncthreads();
    if (tm == 0) {
        smf[LROWU + prow]     = iv0 / em0;   // 1 / (lm * exp(m))
        smf[LROWU + prow + 8] = iv1 / em1;
    }
    __syncthreads();

    // ---- write O (normalized) ----
    #pragma unroll
    for (int vt = 0; vt < 8; vt++) {
        int c = vt * 8 + 2 * tm;
        *(float2*)(oo + (size_t)prow * H_ + c)       = make_float2(O[vt][0] * iv0, O[vt][1] * iv0);
        *(float2*)(oo + (size_t)(prow + 8) * H_ + c) = make_float2(O[vt][2] * iv1, O[vt][3] * iv1);
    }

    // ---- rescale p: coalesced sweep over this CTA's 128x2048 slice ----
    for (int i = tid; i < 128 * 512; i += NT) {
        int row = i >> 9, c4 = i & 511;
        float il = smf[LROWU + row];
        float4* g = (float4*)(pp + (size_t)row * S_) + c4;
        float4 vv = __ldcs(g);
        vv.x *= il; vv.y *= il; vv.z *= il; vv.w *= il;
        __stcs(g, vv);
    }
}

extern "C" void kernel_launch(void* const* d_in, const int* in_sizes, int n_in,
                              void* d_out, int out_size)
{
    const float* q    = (const float*)d_in[0];
    const float* keys = (const float*)d_in[1];
    const float* vals = (const float*)d_in[2];
    const int*   mask = (const int*)d_in[3];
    float* out = (float*)d_out;

    cudaFuncSetAttribute(attn_h2, cudaFuncAttributeMaxDynamicSharedMemorySize, SMEM_BYTES);
    attn_h2<<<B_ * (T_ / 128), NT, SMEM_BYTES>>>(q, keys, vals, mask, out);
}

// round 9
// speedup vs baseline: 1.5532x; 1.2157x over previous
#include <cuda_runtime.h>
#include <cuda_fp16.h>
#include <cstdint>

static constexpr int B_ = 8, T_ = 2048, S_ = 2048, H_ = 64;
static constexpr int NT = 256;

// smem u32-unit offsets
static constexpr int KHI = 0;        // K hi: [s:128][kpair:32] stride 36  (reused as OBUF in epilogue)
static constexpr int KLO = 4608;
static constexpr int VHI = 9216;     // V hi: [h:64][spair:64] stride 68
static constexpr int VLO = 13568;
static constexpr int RINV   = 17920; // 64 floats: per-row 1/(L0+L1)
static constexpr int LBUF   = 17984; // 128 floats: L = lm*em per row per s-half
static constexpr int MBITSU = 18112; // 4 u32 mask bits
static constexpr int SMEMU  = 18116;
static constexpr int SMEM_BYTES = SMEMU * 4;   // ~72.5 KB -> 2 CTAs/SM
static constexpr int OBUF = 0;       // epilogue: 64 rows x 68 stride (fits in K region)

__device__ __forceinline__ void mma16(float* d, const uint32_t* a, uint32_t b0, uint32_t b1) {
    asm volatile(
        "mma.sync.aligned.m16n8k16.row.col.f32.f16.f16.f32 "
        "{%0,%1,%2,%3}, {%4,%5,%6,%7}, {%8,%9}, {%0,%1,%2,%3};"
        : "+f"(d[0]), "+f"(d[1]), "+f"(d[2]), "+f"(d[3])
        : "r"(a[0]), "r"(a[1]), "r"(a[2]), "r"(a[3]), "r"(b0), "r"(b1));
}

// split (x,y) into packed fp16 hi pair (returned) and lo-residual pair (out param)
__device__ __forceinline__ uint32_t packhl(float x, float y, uint32_t& lo) {
    __half hx = __float2half_rn(x), hy = __float2half_rn(y);
    __half2 L = __floats2half2_rn(x - __half2float(hx), y - __half2float(hy));
    __half2 Hh = __halves2half2(hx, hy);
    lo = *(uint32_t*)&L;
    return *(uint32_t*)&Hh;
}

extern __shared__ uint32_t smu[];

__global__ void __launch_bounds__(NT, 2)
attn_h3(const float* __restrict__ q, const float* __restrict__ k,
        const float* __restrict__ v, const int* __restrict__ mask,
        float* __restrict__ out)
{
    const int tid = threadIdx.x;
    const int w = tid >> 5, lane = tid & 31;
    const int n_ = lane >> 2, tm = lane & 3;
    const int bx = blockIdx.x;
    const int b = bx >> 5, t0 = (bx & 31) << 6;     // 64-row tiles, 32 per batch
    const int slab = w & 3, shalf = w >> 2;         // 4 row-slabs x 2 s-halves

    const float* qb = q + ((size_t)b * T_ + t0) * H_;
    const float* kb = k + (size_t)b * S_ * H_;
    const float* vb = v + (size_t)b * S_ * H_;
    const int*   mb = mask + (size_t)b * S_;
    float* pp = out + (size_t)B_ * T_ * H_ + ((size_t)b * T_ + t0) * S_;
    float* oo = out + ((size_t)b * T_ + t0) * H_;

    float* smf = (float*)smu;
    const int prow = 16 * slab + n_;                // 0..63

    // ---- Q fragments: 4 k16-chunks, pre-split fp16 hi/lo, in registers ----
    uint32_t qh[4][4], ql[4][4];
    #pragma unroll
    for (int kc = 0; kc < 4; kc++) {
        const int base = kc * 16 + 2 * tm;
        float2 x0 = *(const float2*)(qb + prow * 64 + base);
        float2 x1 = *(const float2*)(qb + (prow + 8) * 64 + base);
        float2 x2 = *(const float2*)(qb + prow * 64 + base + 8);
        float2 x3 = *(const float2*)(qb + (prow + 8) * 64 + base + 8);
        qh[kc][0] = packhl(x0.x, x0.y, ql[kc][0]);
        qh[kc][1] = packhl(x1.x, x1.y, ql[kc][1]);
        qh[kc][2] = packhl(x2.x, x2.y, ql[kc][2]);
        qh[kc][3] = packhl(x3.x, x3.y, ql[kc][3]);
    }

    float O[8][4];
    #pragma unroll
    for (int i = 0; i < 8; i++)
        #pragma unroll
        for (int jj = 0; jj < 4; jj++) O[i][jj] = 0.0f;
    // flash state (this warp's s-half only); em = exp(m) cached
    float m0 = -3.0e38f, m1 = -3.0e38f, lm0 = 0.0f, lm1 = 0.0f;
    float em0 = 0.0f, em1 = 0.0f;
    const float LOGT = 10.0f;   // common path keeps e <= e^10 ~ 22026 << 65504

    const int ks_s  = tid >> 4;          // K staging: s row (+16 per it)
    const int ks_k4 = (tid & 15) * 4;    // first of 4 k values
    const int vs_sp = tid & 63;          // V staging: s-pair
    const int vs_h0 = (tid >> 6) * 16;   // h block of 16

    for (int j = 0; j < 16; j++) {
        const int s0 = j << 7;
        __syncthreads();   // previous tile's reads complete

        // ---- stage K: hi/lo fp16 pairs, [s][kpair] stride 36 ----
        const float* kt = kb + (size_t)s0 * H_;
        #pragma unroll
        for (int it = 0; it < 8; it++) {
            int s = ks_s + it * 16;
            float4 x = *(const float4*)(kt + s * 64 + ks_k4);
            uint32_t l0, l1;
            uint32_t h0 = packhl(x.x, x.y, l0);
            uint32_t h1 = packhl(x.z, x.w, l1);
            *(uint2*)&smu[KHI + s * 36 + (ks_k4 >> 1)] = make_uint2(h0, h1);
            *(uint2*)&smu[KLO + s * 36 + (ks_k4 >> 1)] = make_uint2(l0, l1);
        }
        // ---- stage V: pairs (V[2sp][h], V[2sp+1][h]) at [h][sp] stride 68 ----
        {
            const float* r0 = vb + (size_t)(s0 + 2 * vs_sp) * H_ + vs_h0;
            const float* r1 = r0 + H_;
            #pragma unroll
            for (int i = 0; i < 4; i++) {
                float4 a = *(const float4*)(r0 + i * 4);
                float4 c = *(const float4*)(r1 + i * 4);
                uint32_t lo;
                int hh = vs_h0 + i * 4;
                uint32_t hi0 = packhl(a.x, c.x, lo);
                smu[VHI + (hh + 0) * 68 + vs_sp] = hi0; smu[VLO + (hh + 0) * 68 + vs_sp] = lo;
                uint32_t hi1 = packhl(a.y, c.y, lo);
                smu[VHI + (hh + 1) * 68 + vs_sp] = hi1; smu[VLO + (hh + 1) * 68 + vs_sp] = lo;
                uint32_t hi2 = packhl(a.z, c.z, lo);
                smu[VHI + (hh + 2) * 68 + vs_sp] = hi2; smu[VLO + (hh + 2) * 68 + vs_sp] = lo;
                uint32_t hi3 = packhl(a.w, c.w, lo);
                smu[VHI + (hh + 3) * 68 + vs_sp] = hi3; smu[VLO + (hh + 3) * 68 + vs_sp] = lo;
            }
        }
        if (tid < 128) {
            unsigned mv = __ballot_sync(0xffffffffu, mb[s0 + tid] != 0);
            if (lane == 0) smu[MBITSU + w] = mv;
        }
        __syncthreads();

        const uint32_t* Kh = smu + KHI;
        const uint32_t* Kl = smu + KLO;
        const uint32_t* Vh = smu + VHI;
        const uint32_t* Vl = smu + VLO;

        // this warp handles strips [shalf*8, shalf*8+8) -> 4 strip-pairs
        #pragma unroll 2
        for (int ntp = 0; ntp < 4; ntp++) {
            const int ntpg = shalf * 4 + ntp;       // global strip-pair index (0..7)
            float sv[2][4];
            uint32_t bt[2][2];
            // ---- raw QK^T scores for the two 8-col strips ----
            #pragma unroll
            for (int si = 0; si < 2; si++) {
                const int strip = ntpg * 2 + si;
                float dh[4] = {0.f,0.f,0.f,0.f}, dm[4] = {0.f,0.f,0.f,0.f}, dl[4] = {0.f,0.f,0.f,0.f};
                const int kb0 = (strip * 8 + n_) * 36 + tm;
                #pragma unroll
                for (int kc = 0; kc < 4; kc++) {
                    uint32_t bh0 = Kh[kb0 + kc * 8], bh1 = Kh[kb0 + kc * 8 + 4];
                    uint32_t bl0 = Kl[kb0 + kc * 8], bl1 = Kl[kb0 + kc * 8 + 4];
                    mma16(dh, qh[kc], bh0, bh1);
                    mma16(dm, ql[kc], bh0, bh1);
                    mma16(dl, qh[kc], bl0, bl1);
                }
                #pragma unroll
                for (int x = 0; x < 4; x++) sv[si][x] = dh[x] + dm[x] + dl[x];
                uint32_t wb = smu[MBITSU + (strip >> 2)];
                int sh = ((strip & 3) << 3) + 2 * tm;
                bt[si][0] = (wb >> sh) & 1u;
                bt[si][1] = (wb >> (sh + 1)) & 1u;
            }
            // ---- per-lane masked max for overflow check ----
            float t0 = -3.0e38f, t1 = -3.0e38f;
            #pragma unroll
            for (int si = 0; si < 2; si++) {
                if (bt[si][0]) { t0 = fmaxf(t0, sv[si][0]); t1 = fmaxf(t1, sv[si][2]); }
                if (bt[si][1]) { t0 = fmaxf(t0, sv[si][1]); t1 = fmaxf(t1, sv[si][3]); }
            }
            // ---- lazy max: exact slow path only when needed ----
            bool big = (t0 > m0 + LOGT) || (t1 > m1 + LOGT);
            if (__any_sync(0xffffffffu, big)) {
                t0 = fmaxf(t0, __shfl_xor_sync(0xffffffffu, t0, 1));
                t0 = fmaxf(t0, __shfl_xor_sync(0xffffffffu, t0, 2));
                t1 = fmaxf(t1, __shfl_xor_sync(0xffffffffu, t1, 1));
                t1 = fmaxf(t1, __shfl_xor_sync(0xffffffffu, t1, 2));
                float m0n = fmaxf(m0, t0), m1n = fmaxf(m1, t1);
                float f0 = __expf(m0 - m0n), f1 = __expf(m1 - m1n);
                lm0 *= f0; lm1 *= f1;
                #pragma unroll
                for (int vt = 0; vt < 8; vt++) {
                    O[vt][0] *= f0; O[vt][1] *= f0;
                    O[vt][2] *= f1; O[vt][3] *= f1;
                }
                m0 = m0n; m1 = m1n;
                em0 = __expf(m0); em1 = __expf(m1);
            }

            // ---- exp, raw p store (= exp(s), m-independent), pack A-frags ----
            float e[2][4];
            #pragma unroll
            for (int si = 0; si < 2; si++) {
                e[si][0] = bt[si][0] ? __expf(sv[si][0] - m0) : 0.0f;
                e[si][1] = bt[si][1] ? __expf(sv[si][1] - m0) : 0.0f;
                e[si][2] = bt[si][0] ? __expf(sv[si][2] - m1) : 0.0f;
                e[si][3] = bt[si][1] ? __expf(sv[si][3] - m1) : 0.0f;
                lm0 += e[si][0] + e[si][1];
                lm1 += e[si][2] + e[si][3];
                const int cg = (ntpg * 2 + si) * 8 + 2 * tm;
                __stcs((float2*)(pp + (size_t)prow * S_ + s0 + cg),
                       make_float2(e[si][0] * em0, e[si][1] * em0));
                __stcs((float2*)(pp + (size_t)(prow + 8) * S_ + s0 + cg),
                       make_float2(e[si][2] * em1, e[si][3] * em1));
            }
            uint32_t pah[4], pal[4];
            pah[0] = packhl(e[0][0], e[0][1], pal[0]);
            pah[1] = packhl(e[0][2], e[0][3], pal[1]);
            pah[2] = packhl(e[1][0], e[1][1], pal[2]);
            pah[3] = packhl(e[1][2], e[1][3], pal[3]);

            // ---- PV for this k16 strip-pair: 8 independent O chains ----
            const int vb0 = ntpg * 8 + tm;
            #pragma unroll
            for (int vt = 0; vt < 8; vt++) {
                const int a0 = (vt * 8 + n_) * 68 + vb0;
                uint32_t vh0_ = Vh[a0], vh1_ = Vh[a0 + 4];
                uint32_t vl0_ = Vl[a0], vl1_ = Vl[a0 + 4];
                mma16(O[vt], pah, vh0_, vh1_);
                mma16(O[vt], pal, vh0_, vh1_);
                mma16(O[vt], pah, vl0_, vl1_);
            }
        }
    }

    // ================= epilogue: combine the two s-halves =================
    // quad-reduce lm; this warp's row normalizer piece L = lm * em
    lm0 += __shfl_xor_sync(0xffffffffu, lm0, 1);
    lm0 += __shfl_xor_sync(0xffffffffu, lm0, 2);
    lm1 += __shfl_xor_sync(0xffffffffu, lm1, 1);
    lm1 += __shfl_xor_sync(0xffffffffu, lm1, 2);

    // scale O to the common (m-free) frame: Os = O * em
    #pragma unroll
    for (int vt = 0; vt < 8; vt++) {
        O[vt][0] *= em0; O[vt][1] *= em0;
        O[vt][2] *= em1; O[vt][3] *= em1;
    }

    __syncthreads();   // done with K/V smem; reuse K region as OBUF
    if (tm == 0) {
        smf[LBUF + shalf * 64 + prow]     = lm0 * em0;
        smf[LBUF + shalf * 64 + prow + 8] = lm1 * em1;
    }
    if (shalf == 0) {
        #pragma unroll
        for (int vt = 0; vt < 8; vt++) {
            int c = vt * 8 + 2 * tm;
            *(float2*)&smf[OBUF + prow * 68 + c]       = make_float2(O[vt][0], O[vt][1]);
            *(float2*)&smf[OBUF + (prow + 8) * 68 + c] = make_float2(O[vt][2], O[vt][3]);
        }
    }
    __syncthreads();
    if (tid < 64) smf[RINV + tid] = 1.0f / (smf[LBUF + tid] + smf[LBUF + 64 + tid]);
    __syncthreads();

    if (shalf == 1) {
        const float iv0 = smf[RINV + prow];
        const float iv1 = smf[RINV + prow + 8];
        #pragma unroll
        for (int vt = 0; vt < 8; vt++) {
            int c = vt * 8 + 2 * tm;
            float2 pa = *(const float2*)&smf[OBUF + prow * 68 + c];
            float2 pb = *(const float2*)&smf[OBUF + (prow + 8) * 68 + c];
            *(float2*)(oo + (size_t)prow * H_ + c) =
                make_float2((pa.x + O[vt][0]) * iv0, (pa.y + O[vt][1]) * iv0);
            *(float2*)(oo + (size_t)(prow + 8) * H_ + c) =
                make_float2((pb.x + O[vt][2]) * iv1, (pb.y + O[vt][3]) * iv1);
        }
    }

    // ---- rescale p: coalesced sweep over this CTA's 64x2048 slice ----
    for (int i = tid; i < 64 * 512; i += NT) {
        int row = i >> 9, c4 = i & 511;
        float il = smf[RINV + row];
        float4* g = (float4*)(pp + (size_t)row * S_) + c4;
        float4 vv = __ldcs(g);
        vv.x *= il; vv.y *= il; vv.z *= il; vv.w *= il;
        __stcs(g, vv);
    }
}

extern "C" void kernel_launch(void* const* d_in, const int* in_sizes, int n_in,
                              void* d_out, int out_size)
{
    const float* q    = (const float*)d_in[0];
    const float* keys = (const float*)d_in[1];
    const float* vals = (const float*)d_in[2];
    const int*   mask = (const int*)d_in[3];
    float* out = (float*)d_out;

    cudaFuncSetAttribute(attn_h3, cudaFuncAttributeMaxDynamicSharedMemorySize, SMEM_BYTES);
    attn_h3<<<B_ * (T_ / 64), NT, SMEM_BYTES>>>(q, keys, vals, mask, out);
}

// round 10
// speedup vs baseline: 1.6234x; 1.0452x over previous
#include <cuda_runtime.h>
#include <cuda_fp16.h>
#include <cstdint>

static constexpr int B_ = 8, T_ = 2048, S_ = 2048, H_ = 64;
static constexpr int NT = 256;

// smem u32-unit offsets
static constexpr int KHI = 0;        // K hi: [s:128][kpair:32] stride 36 (reused as OBUF in epilogue)
static constexpr int KLO = 4608;
static constexpr int VHI = 9216;     // V hi: [h:64][spair:64] stride 68
static constexpr int RINV   = 13568; // 64 floats: per-row 1/(L0+L1)
static constexpr int LBUF   = 13632; // 128 floats: L = lm*em per row per s-half
static constexpr int MBITSU = 13760; // 4 u32 mask bits
static constexpr int SMEMU  = 13764;
static constexpr int SMEM_BYTES = SMEMU * 4;   // ~55 KB -> 2 CTAs/SM (reg-bound anyway)
static constexpr int OBUF = 0;       // epilogue: 64 rows x 68 stride (fits in K region)

__device__ __forceinline__ void mma16(float* d, const uint32_t* a, uint32_t b0, uint32_t b1) {
    asm volatile(
        "mma.sync.aligned.m16n8k16.row.col.f32.f16.f16.f32 "
        "{%0,%1,%2,%3}, {%4,%5,%6,%7}, {%8,%9}, {%0,%1,%2,%3};"
        : "+f"(d[0]), "+f"(d[1]), "+f"(d[2]), "+f"(d[3])
        : "r"(a[0]), "r"(a[1]), "r"(a[2]), "r"(a[3]), "r"(b0), "r"(b1));
}

// split (x,y) into packed fp16 hi pair (returned) and lo-residual pair (out param)
__device__ __forceinline__ uint32_t packhl(float x, float y, uint32_t& lo) {
    __half hx = __float2half_rn(x), hy = __float2half_rn(y);
    __half2 L = __floats2half2_rn(x - __half2float(hx), y - __half2float(hy));
    __half2 Hh = __halves2half2(hx, hy);
    lo = *(uint32_t*)&L;
    return *(uint32_t*)&Hh;
}

// plain fp16 pair pack (no residual) — for V
__device__ __forceinline__ uint32_t packh(float x, float y) {
    __half2 Hh = __floats2half2_rn(x, y);
    return *(uint32_t*)&Hh;
}

extern __shared__ uint32_t smu[];

__global__ void __launch_bounds__(NT, 2)
attn_h4(const float* __restrict__ q, const float* __restrict__ k,
        const float* __restrict__ v, const int* __restrict__ mask,
        float* __restrict__ out)
{
    const int tid = threadIdx.x;
    const int w = tid >> 5, lane = tid & 31;
    const int n_ = lane >> 2, tm = lane & 3;
    const int bx = blockIdx.x;
    const int b = bx >> 5, t0 = (bx & 31) << 6;     // 64-row tiles, 32 per batch
    const int slab = w & 3, shalf = w >> 2;         // 4 row-slabs x 2 s-halves

    const float* qb = q + ((size_t)b * T_ + t0) * H_;
    const float* kb = k + (size_t)b * S_ * H_;
    const float* vb = v + (size_t)b * S_ * H_;
    const int*   mb = mask + (size_t)b * S_;
    float* pp = out + (size_t)B_ * T_ * H_ + ((size_t)b * T_ + t0) * S_;
    float* oo = out + ((size_t)b * T_ + t0) * H_;

    float* smf = (float*)smu;
    const int prow = 16 * slab + n_;                // 0..63

    // ---- Q fragments: 4 k16-chunks, pre-split fp16 hi/lo, in registers ----
    uint32_t qh[4][4], ql[4][4];
    #pragma unroll
    for (int kc = 0; kc < 4; kc++) {
        const int base = kc * 16 + 2 * tm;
        float2 x0 = *(const float2*)(qb + prow * 64 + base);
        float2 x1 = *(const float2*)(qb + (prow + 8) * 64 + base);
        float2 x2 = *(const float2*)(qb + prow * 64 + base + 8);
        float2 x3 = *(const float2*)(qb + (prow + 8) * 64 + base + 8);
        qh[kc][0] = packhl(x0.x, x0.y, ql[kc][0]);
        qh[kc][1] = packhl(x1.x, x1.y, ql[kc][1]);
        qh[kc][2] = packhl(x2.x, x2.y, ql[kc][2]);
        qh[kc][3] = packhl(x3.x, x3.y, ql[kc][3]);
    }

    float O[8][4];
    #pragma unroll
    for (int i = 0; i < 8; i++)
        #pragma unroll
        for (int jj = 0; jj < 4; jj++) O[i][jj] = 0.0f;
    // flash state (this warp's s-half only); em = exp(m) cached
    float m0 = -3.0e38f, m1 = -3.0e38f, lm0 = 0.0f, lm1 = 0.0f;
    float em0 = 0.0f, em1 = 0.0f;
    const float LOGT = 10.0f;   // common path keeps e <= e^10 ~ 22026 << 65504

    const int ks_s  = tid >> 4;          // K staging: s row (+16 per it)
    const int ks_k4 = (tid & 15) * 4;    // first of 4 k values
    const int vs_sp = tid & 63;          // V staging: s-pair
    const int vs_h0 = (tid >> 6) * 16;   // h block of 16

    for (int j = 0; j < 16; j++) {
        const int s0 = j << 7;
        __syncthreads();   // previous tile's reads complete

        // ---- stage K: hi/lo fp16 pairs, [s][kpair] stride 36 ----
        const float* kt = kb + (size_t)s0 * H_;
        #pragma unroll
        for (int it = 0; it < 8; it++) {
            int s = ks_s + it * 16;
            float4 x = *(const float4*)(kt + s * 64 + ks_k4);
            uint32_t l0, l1;
            uint32_t h0 = packhl(x.x, x.y, l0);
            uint32_t h1 = packhl(x.z, x.w, l1);
            *(uint2*)&smu[KHI + s * 36 + (ks_k4 >> 1)] = make_uint2(h0, h1);
            *(uint2*)&smu[KLO + s * 36 + (ks_k4 >> 1)] = make_uint2(l0, l1);
        }
        // ---- stage V (hi only): pairs (V[2sp][h], V[2sp+1][h]) at [h][sp] stride 68 ----
        {
            const float* r0 = vb + (size_t)(s0 + 2 * vs_sp) * H_ + vs_h0;
            const float* r1 = r0 + H_;
            #pragma unroll
            for (int i = 0; i < 4; i++) {
                float4 a = *(const float4*)(r0 + i * 4);
                float4 c = *(const float4*)(r1 + i * 4);
                int hh = vs_h0 + i * 4;
                smu[VHI + (hh + 0) * 68 + vs_sp] = packh(a.x, c.x);
                smu[VHI + (hh + 1) * 68 + vs_sp] = packh(a.y, c.y);
                smu[VHI + (hh + 2) * 68 + vs_sp] = packh(a.z, c.z);
                smu[VHI + (hh + 3) * 68 + vs_sp] = packh(a.w, c.w);
            }
        }
        if (tid < 128) {
            unsigned mv = __ballot_sync(0xffffffffu, mb[s0 + tid] != 0);
            if (lane == 0) smu[MBITSU + w] = mv;
        }
        __syncthreads();

        const uint32_t* Kh = smu + KHI;
        const uint32_t* Kl = smu + KLO;
        const uint32_t* Vh = smu + VHI;

        // this warp handles strips [shalf*8, shalf*8+8) -> 4 strip-pairs
        #pragma unroll 2
        for (int ntp = 0; ntp < 4; ntp++) {
            const int ntpg = shalf * 4 + ntp;       // global strip-pair index (0..7)
            float sv[2][4];
            uint32_t bt[2][2];
            // ---- raw QK^T scores for the two 8-col strips ----
            #pragma unroll
            for (int si = 0; si < 2; si++) {
                const int strip = ntpg * 2 + si;
                float dh[4] = {0.f,0.f,0.f,0.f}, dm[4] = {0.f,0.f,0.f,0.f}, dl[4] = {0.f,0.f,0.f,0.f};
                const int kb0 = (strip * 8 + n_) * 36 + tm;
                #pragma unroll
                for (int kc = 0; kc < 4; kc++) {
                    uint32_t bh0 = Kh[kb0 + kc * 8], bh1 = Kh[kb0 + kc * 8 + 4];
                    uint32_t bl0 = Kl[kb0 + kc * 8], bl1 = Kl[kb0 + kc * 8 + 4];
                    mma16(dh, qh[kc], bh0, bh1);
                    mma16(dm, ql[kc], bh0, bh1);
                    mma16(dl, qh[kc], bl0, bl1);
                }
                #pragma unroll
                for (int x = 0; x < 4; x++) sv[si][x] = dh[x] + dm[x] + dl[x];
                uint32_t wb = smu[MBITSU + (strip >> 2)];
                int sh = ((strip & 3) << 3) + 2 * tm;
                bt[si][0] = (wb >> sh) & 1u;
                bt[si][1] = (wb >> (sh + 1)) & 1u;
            }
            // ---- per-lane masked max for overflow check ----
            float t0 = -3.0e38f, t1 = -3.0e38f;
            #pragma unroll
            for (int si = 0; si < 2; si++) {
                if (bt[si][0]) { t0 = fmaxf(t0, sv[si][0]); t1 = fmaxf(t1, sv[si][2]); }
                if (bt[si][1]) { t0 = fmaxf(t0, sv[si][1]); t1 = fmaxf(t1, sv[si][3]); }
            }
            // ---- lazy max: exact slow path only when needed ----
            bool big = (t0 > m0 + LOGT) || (t1 > m1 + LOGT);
            if (__any_sync(0xffffffffu, big)) {
                t0 = fmaxf(t0, __shfl_xor_sync(0xffffffffu, t0, 1));
                t0 = fmaxf(t0, __shfl_xor_sync(0xffffffffu, t0, 2));
                t1 = fmaxf(t1, __shfl_xor_sync(0xffffffffu, t1, 1));
                t1 = fmaxf(t1, __shfl_xor_sync(0xffffffffu, t1, 2));
                float m0n = fmaxf(m0, t0), m1n = fmaxf(m1, t1);
                float f0 = __expf(m0 - m0n), f1 = __expf(m1 - m1n);
                lm0 *= f0; lm1 *= f1;
                #pragma unroll
                for (int vt = 0; vt < 8; vt++) {
                    O[vt][0] *= f0; O[vt][1] *= f0;
                    O[vt][2] *= f1; O[vt][3] *= f1;
                }
                m0 = m0n; m1 = m1n;
                em0 = __expf(m0); em1 = __expf(m1);
            }

            // ---- exp, raw p store (= exp(s), m-independent), pack A-frags ----
            float e[2][4];
            #pragma unroll
            for (int si = 0; si < 2; si++) {
                e[si][0] = bt[si][0] ? __expf(sv[si][0] - m0) : 0.0f;
                e[si][1] = bt[si][1] ? __expf(sv[si][1] - m0) : 0.0f;
                e[si][2] = bt[si][0] ? __expf(sv[si][2] - m1) : 0.0f;
                e[si][3] = bt[si][1] ? __expf(sv[si][3] - m1) : 0.0f;
                lm0 += e[si][0] + e[si][1];
                lm1 += e[si][2] + e[si][3];
                const int cg = (ntpg * 2 + si) * 8 + 2 * tm;
                __stcs((float2*)(pp + (size_t)prow * S_ + s0 + cg),
                       make_float2(e[si][0] * em0, e[si][1] * em0));
                __stcs((float2*)(pp + (size_t)(prow + 8) * S_ + s0 + cg),
                       make_float2(e[si][2] * em1, e[si][3] * em1));
            }
            uint32_t pah[4], pal[4];
            pah[0] = packhl(e[0][0], e[0][1], pal[0]);
            pah[1] = packhl(e[0][2], e[0][3], pal[1]);
            pah[2] = packhl(e[1][0], e[1][1], pal[2]);
            pah[3] = packhl(e[1][2], e[1][3], pal[3]);

            // ---- PV for this k16 strip-pair: 8 independent O chains, V in plain fp16 ----
            const int vb0 = ntpg * 8 + tm;
            #pragma unroll
            for (int vt = 0; vt < 8; vt++) {
                const int a0 = (vt * 8 + n_) * 68 + vb0;
                uint32_t vh0_ = Vh[a0], vh1_ = Vh[a0 + 4];
                mma16(O[vt], pah, vh0_, vh1_);
                mma16(O[vt], pal, vh0_, vh1_);
            }
        }
    }

    // ================= epilogue: combine the two s-halves =================
    lm0 += __shfl_xor_sync(0xffffffffu, lm0, 1);
    lm0 += __shfl_xor_sync(0xffffffffu, lm0, 2);
    lm1 += __shfl_xor_sync(0xffffffffu, lm1, 1);
    lm1 += __shfl_xor_sync(0xffffffffu, lm1, 2);

    // scale O to the common (m-free) frame: Os = O * em
    #pragma unroll
    for (int vt = 0; vt < 8; vt++) {
        O[vt][0] *= em0; O[vt][1] *= em0;
        O[vt][2] *= em1; O[vt][3] *= em1;
    }

    __syncthreads();   // done with K/V smem; reuse K region as OBUF
    if (tm == 0) {
        smf[LBUF + shalf * 64 + prow]     = lm0 * em0;
        smf[LBUF + shalf * 64 + prow + 8] = lm1 * em1;
    }
    if (shalf == 0) {
        #pragma unroll
        for (int vt = 0; vt < 8; vt++) {
            int c = vt * 8 + 2 * tm;
            *(float2*)&smf[OBUF + prow * 68 + c]       = make_float2(O[vt][0], O[vt][1]);
            *(float2*)&smf[OBUF + (prow + 8) * 68 + c] = make_float2(O[vt][2], O[vt][3]);
        }
    }
    __syncthreads();
    if (tid < 64) smf[RINV + tid] = 1.0f / (smf[LBUF + tid] + smf[LBUF + 64 + tid]);
    __syncthreads();

    if (shalf == 1) {
        const float iv0 = smf[RINV + prow];
        const float iv1 = smf[RINV + prow + 8];
        #pragma unroll
        for (int vt = 0; vt < 8; vt++) {
            int c = vt * 8 + 2 * tm;
            float2 pa = *(const float2*)&smf[OBUF + prow * 68 + c];
            float2 pb = *(const float2*)&smf[OBUF + (prow + 8) * 68 + c];
            *(float2*)(oo + (size_t)prow * H_ + c) =
                make_float2((pa.x + O[vt][0]) * iv0, (pa.y + O[vt][1]) * iv0);
            *(float2*)(oo + (size_t)(prow + 8) * H_ + c) =
                make_float2((pb.x + O[vt][2]) * iv1, (pb.y + O[vt][3]) * iv1);
        }
    }

    // ---- rescale p: coalesced sweep over this CTA's 64x2048 slice ----
    for (int i = tid; i < 64 * 512; i += NT) {
        int row = i >> 9, c4 = i & 511;
        float il = smf[RINV + row];
        float4* g = (float4*)(pp + (size_t)row * S_) + c4;
        float4 vv = __ldcs(g);
        vv.x *= il; vv.y *= il; vv.z *= il; vv.w *= il;
        __stcs(g, vv);
    }
}

extern "C" void kernel_launch(void* const* d_in, const int* in_sizes, int n_in,
                              void* d_out, int out_size)
{
    const float* q    = (const float*)d_in[0];
    const float* keys = (const float*)d_in[1];
    const float* vals = (const float*)d_in[2];
    const int*   mask = (const int*)d_in[3];
    float* out = (float*)d_out;

    cudaFuncSetAttribute(attn_h4, cudaFuncAttributeMaxDynamicSharedMemorySize, SMEM_BYTES);
    attn_h4<<<B_ * (T_ / 64), NT, SMEM_BYTES>>>(q, keys, vals, mask, out);
}

// round 11
// speedup vs baseline: 1.8399x; 1.1333x over previous
#include <cuda_runtime.h>
#include <cuda_fp16.h>
#include <cstdint>

static constexpr int B_ = 8, T_ = 2048, S_ = 2048, H_ = 64;
static constexpr int NT = 256;

// smem u32-unit offsets
static constexpr int KHI = 0;        // K hi: [s:128][pos:32] stride 40, pair-interleaved
static constexpr int KLO = 5120;
static constexpr int VHI = 10240;    // V hi: [h:64][pos:64] stride 72, pair-interleaved + XOR swizzle
static constexpr int RINV   = 14848; // 64 floats: per-row 1/(L0+L1)
static constexpr int LBUF   = 14912; // 128 floats: L = lm*em per row per s-half
static constexpr int MBITSU = 15040; // 4 u32 mask bits
static constexpr int SMEMU  = 15044;
static constexpr int SMEM_BYTES = SMEMU * 4;   // ~59 KB -> 2 CTAs/SM
static constexpr int OBUF = 0;       // epilogue scratch: 64 rows x 68 stride (in K region)

__device__ __forceinline__ void mma16(float* d, const uint32_t* a, uint32_t b0, uint32_t b1) {
    asm volatile(
        "mma.sync.aligned.m16n8k16.row.col.f32.f16.f16.f32 "
        "{%0,%1,%2,%3}, {%4,%5,%6,%7}, {%8,%9}, {%0,%1,%2,%3};"
        : "+f"(d[0]), "+f"(d[1]), "+f"(d[2]), "+f"(d[3])
        : "r"(a[0]), "r"(a[1]), "r"(a[2]), "r"(a[3]), "r"(b0), "r"(b1));
}

__device__ __forceinline__ uint32_t packhl(float x, float y, uint32_t& lo) {
    __half hx = __float2half_rn(x), hy = __float2half_rn(y);
    __half2 L = __floats2half2_rn(x - __half2float(hx), y - __half2float(hy));
    __half2 Hh = __halves2half2(hx, hy);
    lo = *(uint32_t*)&L;
    return *(uint32_t*)&Hh;
}

__device__ __forceinline__ uint32_t packh(float x, float y) {
    __half2 Hh = __floats2half2_rn(x, y);
    return *(uint32_t*)&Hh;
}

// V XOR swizzle: same function on store & load sides (bits 1-4, bit0 untouched)
__device__ __forceinline__ int swzv(int h) {
    return ((h & 3) << 1) ^ (((h >> 2) & 7) << 2);
}

extern __shared__ uint32_t smu[];

__global__ void __launch_bounds__(NT, 2)
attn_h5(const float* __restrict__ q, const float* __restrict__ k,
        const float* __restrict__ v, const int* __restrict__ mask,
        float* __restrict__ out)
{
    const int tid = threadIdx.x;
    const int w = tid >> 5, lane = tid & 31;
    const int n_ = lane >> 2, tm = lane & 3;
    const int bx = blockIdx.x;
    const int b = bx >> 5, t0 = (bx & 31) << 6;     // 64-row tiles, 32 per batch
    const int slab = w & 3, shalf = w >> 2;         // 4 row-slabs x 2 s-halves

    const float* qb = q + ((size_t)b * T_ + t0) * H_;
    const float* kb = k + (size_t)b * S_ * H_;
    const float* vb = v + (size_t)b * S_ * H_;
    const int*   mb = mask + (size_t)b * S_;
    float* pp = out + (size_t)B_ * T_ * H_ + ((size_t)b * T_ + t0) * S_;
    float* oo = out + ((size_t)b * T_ + t0) * H_;

    float* smf = (float*)smu;
    const int prow = 16 * slab + n_;                // 0..63

    // ---- Q fragments: 4 k16-chunks, pre-split fp16 hi/lo, in registers ----
    uint32_t qh[4][4], ql[4][4];
    #pragma unroll
    for (int kc = 0; kc < 4; kc++) {
        const int base = kc * 16 + 2 * tm;
        float2 x0 = *(const float2*)(qb + prow * 64 + base);
        float2 x1 = *(const float2*)(qb + (prow + 8) * 64 + base);
        float2 x2 = *(const float2*)(qb + prow * 64 + base + 8);
        float2 x3 = *(const float2*)(qb + (prow + 8) * 64 + base + 8);
        qh[kc][0] = packhl(x0.x, x0.y, ql[kc][0]);
        qh[kc][1] = packhl(x1.x, x1.y, ql[kc][1]);
        qh[kc][2] = packhl(x2.x, x2.y, ql[kc][2]);
        qh[kc][3] = packhl(x3.x, x3.y, ql[kc][3]);
    }

    float O[8][4];
    #pragma unroll
    for (int i = 0; i < 8; i++)
        #pragma unroll
        for (int jj = 0; jj < 4; jj++) O[i][jj] = 0.0f;
    float m0 = -3.0e38f, m1 = -3.0e38f, lm0 = 0.0f, lm1 = 0.0f;
    float em0 = 0.0f, em1 = 0.0f;
    const float LOGT = 10.0f;

    // K staging mapping
    const int ks_s  = tid >> 4;          // row (+16 per it)
    const int ks_k4 = (tid & 15) * 4;    // first of 4 k values
    // precompute K interleaved positions for this thread
    const int kt0 = ks_k4 >> 1;                    // even pair index
    const int kpb = kt0 & ~7;
    const int ku0 = kt0 & 7;                       // even
    const int kp0 = kpb + 2 * (ku0 & 3) + (ku0 >> 2);
    const int kp1 = kp0 + 2;
    // V staging mapping: thread -> (sp, cols cc..cc+3)
    const int vs_spb = w * 2 + (lane >> 4);        // 0..15 (+16 per it)
    const int vs_cc  = 4 * (lane & 15);

    for (int j = 0; j < 16; j++) {
        const int s0 = j << 7;
        __syncthreads();   // previous tile's reads complete

        // ---- stage K: hi/lo fp16 pairs, pair-interleaved, stride 40 ----
        const float* kt = kb + (size_t)s0 * H_;
        #pragma unroll
        for (int it = 0; it < 8; it++) {
            int s = ks_s + it * 16;
            float4 x = *(const float4*)(kt + s * 64 + ks_k4);
            uint32_t l0, l1;
            uint32_t h0 = packhl(x.x, x.y, l0);
            uint32_t h1 = packhl(x.z, x.w, l1);
            smu[KHI + s * 40 + kp0] = h0;
            smu[KHI + s * 40 + kp1] = h1;
            smu[KLO + s * 40 + kp0] = l0;
            smu[KLO + s * 40 + kp1] = l1;
        }
        // ---- stage V: coalesced row sweeps, pack pairs, swizzled STS ----
        #pragma unroll
        for (int it = 0; it < 4; it++) {
            int sp = vs_spb + it * 16;
            const float* rA = vb + (size_t)(s0 + 2 * sp) * H_ + vs_cc;
            float4 a  = *(const float4*)rA;          // row 2sp   (coalesced)
            float4 b4 = *(const float4*)(rA + H_);   // row 2sp+1 (coalesced)
            int qp = (sp & ~7) + 2 * (sp & 3) + ((sp >> 2) & 1);
            smu[VHI + (vs_cc + 0) * 72 + (qp ^ swzv(vs_cc + 0))] = packh(a.x, b4.x);
            smu[VHI + (vs_cc + 1) * 72 + (qp ^ swzv(vs_cc + 1))] = packh(a.y, b4.y);
            smu[VHI + (vs_cc + 2) * 72 + (qp ^ swzv(vs_cc + 2))] = packh(a.z, b4.z);
            smu[VHI + (vs_cc + 3) * 72 + (qp ^ swzv(vs_cc + 3))] = packh(a.w, b4.w);
        }
        if (tid < 128) {
            unsigned mv = __ballot_sync(0xffffffffu, mb[s0 + tid] != 0);
            if (lane == 0) smu[MBITSU + w] = mv;
        }
        __syncthreads();

        // this warp handles strips [shalf*8, shalf*8+8) -> 4 strip-pairs
        #pragma unroll 2
        for (int ntp = 0; ntp < 4; ntp++) {
            const int ntpg = shalf * 4 + ntp;
            float sv[2][4];
            uint32_t bt[2][2];
            // ---- raw QK^T scores for the two 8-col strips ----
            #pragma unroll
            for (int si = 0; si < 2; si++) {
                const int strip = ntpg * 2 + si;
                float dh[4] = {0.f,0.f,0.f,0.f}, dm[4] = {0.f,0.f,0.f,0.f}, dl[4] = {0.f,0.f,0.f,0.f};
                const int kb0 = (strip * 8 + n_) * 40 + 2 * tm;
                #pragma unroll
                for (int kc = 0; kc < 4; kc++) {
                    uint2 bh = *(const uint2*)&smu[KHI + kb0 + kc * 8];
                    uint2 bl = *(const uint2*)&smu[KLO + kb0 + kc * 8];
                    mma16(dh, qh[kc], bh.x, bh.y);
                    mma16(dm, ql[kc], bh.x, bh.y);
                    mma16(dl, qh[kc], bl.x, bl.y);
                }
                #pragma unroll
                for (int x = 0; x < 4; x++) sv[si][x] = dh[x] + dm[x] + dl[x];
                uint32_t wb = smu[MBITSU + (strip >> 2)];
                int sh = ((strip & 3) << 3) + 2 * tm;
                bt[si][0] = (wb >> sh) & 1u;
                bt[si][1] = (wb >> (sh + 1)) & 1u;
            }
            // ---- per-lane masked max for overflow check ----
            float t0_ = -3.0e38f, t1_ = -3.0e38f;
            #pragma unroll
            for (int si = 0; si < 2; si++) {
                if (bt[si][0]) { t0_ = fmaxf(t0_, sv[si][0]); t1_ = fmaxf(t1_, sv[si][2]); }
                if (bt[si][1]) { t0_ = fmaxf(t0_, sv[si][1]); t1_ = fmaxf(t1_, sv[si][3]); }
            }
            // ---- lazy max: exact slow path only when needed ----
            bool big = (t0_ > m0 + LOGT) || (t1_ > m1 + LOGT);
            if (__any_sync(0xffffffffu, big)) {
                t0_ = fmaxf(t0_, __shfl_xor_sync(0xffffffffu, t0_, 1));
                t0_ = fmaxf(t0_, __shfl_xor_sync(0xffffffffu, t0_, 2));
                t1_ = fmaxf(t1_, __shfl_xor_sync(0xffffffffu, t1_, 1));
                t1_ = fmaxf(t1_, __shfl_xor_sync(0xffffffffu, t1_, 2));
                float m0n = fmaxf(m0, t0_), m1n = fmaxf(m1, t1_);
                float f0 = __expf(m0 - m0n), f1 = __expf(m1 - m1n);
                lm0 *= f0; lm1 *= f1;
                #pragma unroll
                for (int vt = 0; vt < 8; vt++) {
                    O[vt][0] *= f0; O[vt][1] *= f0;
                    O[vt][2] *= f1; O[vt][3] *= f1;
                }
                m0 = m0n; m1 = m1n;
                em0 = __expf(m0); em1 = __expf(m1);
            }

            // ---- exp, raw p store (= exp(s)), pack fp16 A-frags ----
            float e[2][4];
            #pragma unroll
            for (int si = 0; si < 2; si++) {
                e[si][0] = bt[si][0] ? __expf(sv[si][0] - m0) : 0.0f;
                e[si][1] = bt[si][1] ? __expf(sv[si][1] - m0) : 0.0f;
                e[si][2] = bt[si][0] ? __expf(sv[si][2] - m1) : 0.0f;
                e[si][3] = bt[si][1] ? __expf(sv[si][3] - m1) : 0.0f;
                lm0 += e[si][0] + e[si][1];
                lm1 += e[si][2] + e[si][3];
                const int cg = (ntpg * 2 + si) * 8 + 2 * tm;
                __stcs((float2*)(pp + (size_t)prow * S_ + s0 + cg),
                       make_float2(e[si][0] * em0, e[si][1] * em0));
                __stcs((float2*)(pp + (size_t)(prow + 8) * S_ + s0 + cg),
                       make_float2(e[si][2] * em1, e[si][3] * em1));
            }
            uint32_t pah[4], pal[4];
            pah[0] = packhl(e[0][0], e[0][1], pal[0]);
            pah[1] = packhl(e[0][2], e[0][3], pal[1]);
            pah[2] = packhl(e[1][0], e[1][1], pal[2]);
            pah[3] = packhl(e[1][2], e[1][3], pal[3]);

            // ---- PV: 8 independent O chains, V pairs via one LDS.64 each ----
            const int xbase = ntpg * 8 + 2 * tm;
            #pragma unroll
            for (int vt = 0; vt < 8; vt++) {
                const int h = vt * 8 + n_;
                uint2 vv = *(const uint2*)&smu[VHI + h * 72 + (xbase ^ swzv(h))];
                mma16(O[vt], pah, vv.x, vv.y);
                mma16(O[vt], pal, vv.x, vv.y);
            }
        }
    }

    // ================= epilogue: combine the two s-halves =================
    lm0 += __shfl_xor_sync(0xffffffffu, lm0, 1);
    lm0 += __shfl_xor_sync(0xffffffffu, lm0, 2);
    lm1 += __shfl_xor_sync(0xffffffffu, lm1, 1);
    lm1 += __shfl_xor_sync(0xffffffffu, lm1, 2);

    #pragma unroll
    for (int vt = 0; vt < 8; vt++) {
        O[vt][0] *= em0; O[vt][1] *= em0;
        O[vt][2] *= em1; O[vt][3] *= em1;
    }

    __syncthreads();   // done with K/V smem; reuse K region as OBUF
    if (tm == 0) {
        smf[LBUF + shalf * 64 + prow]     = lm0 * em0;
        smf[LBUF + shalf * 64 + prow + 8] = lm1 * em1;
    }
    if (shalf == 0) {
        #pragma unroll
        for (int vt = 0; vt < 8; vt++) {
            int c = vt * 8 + 2 * tm;
            *(float2*)&smf[OBUF + prow * 68 + c]       = make_float2(O[vt][0], O[vt][1]);
            *(float2*)&smf[OBUF + (prow + 8) * 68 + c] = make_float2(O[vt][2], O[vt][3]);
        }
    }
    __syncthreads();
    if (tid < 64) smf[RINV + tid] = 1.0f / (smf[LBUF + tid] + smf[LBUF + 64 + tid]);
    __syncthreads();

    if (shalf == 1) {
        const float iv0 = smf[RINV + prow];
        const float iv1 = smf[RINV + prow + 8];
        #pragma unroll
        for (int vt = 0; vt < 8; vt++) {
            int c = vt * 8 + 2 * tm;
            float2 pa = *(const float2*)&smf[OBUF + prow * 68 + c];
            float2 pb = *(const float2*)&smf[OBUF + (prow + 8) * 68 + c];
            *(float2*)(oo + (size_t)prow * H_ + c) =
                make_float2((pa.x + O[vt][0]) * iv0, (pa.y + O[vt][1]) * iv0);
            *(float2*)(oo + (size_t)(prow + 8) * H_ + c) =
                make_float2((pb.x + O[vt][2]) * iv1, (pb.y + O[vt][3]) * iv1);
        }
    }

    // ---- rescale p: coalesced sweep over this CTA's 64x2048 slice ----
    for (int i = tid; i < 64 * 512; i += NT) {
        int row = i >> 9, c4 = i & 511;
        float il = smf[RINV + row];
        float4* g = (float4*)(pp + (size_t)row * S_) + c4;
        float4 vv = __ldcs(g);
        vv.x *= il; vv.y *= il; vv.z *= il; vv.w *= il;
        __stcs(g, vv);
    }
}

extern "C" void kernel_launch(void* const* d_in, const int* in_sizes, int n_in,
                              void* d_out, int out_size)
{
    const float* q    = (const float*)d_in[0];
    const float* keys = (const float*)d_in[1];
    const float* vals = (const float*)d_in[2];
    const int*   mask = (const int*)d_in[3];
    float* out = (float*)d_out;

    cudaFuncSetAttribute(attn_h5, cudaFuncAttributeMaxDynamicSharedMemorySize, SMEM_BYTES);
    attn_h5<<<B_ * (T_ / 64), NT, SMEM_BYTES>>>(q, keys, vals, mask, out);
}

// round 12
// speedup vs baseline: 2.2291x; 1.2115x over previous
#include <cuda_runtime.h>
#include <cuda_fp16.h>
#include <cstdint>

static constexpr int B_ = 8, T_ = 2048, S_ = 2048, H_ = 64;
static constexpr int NT = 256;

// smem u32-unit offsets
static constexpr int KHI = 0;        // K hi: [s:128][pos:32] stride 40, pair-interleaved
static constexpr int KLO = 5120;
static constexpr int VHI = 10240;    // V hi: [h:64][pos:64] stride 72, interleave + XOR swizzle
static constexpr int CIDXU  = 14848; // 2176 u16 compacted col indices (1088 u32)
static constexpr int BITARR = 15936; // 64 u32 mask bits (kept for tail)
static constexpr int OFFU   = 16000; // 64 u32 chunk offsets
static constexpr int RINV   = 16064; // 64 floats: per-row 1/(L0+L1)
static constexpr int LBUF   = 16128; // 128 floats: L = lm*em per row per s-half
static constexpr int SEFFU  = 16256;
static constexpr int SMEMU  = 16260;
static constexpr int SMEM_BYTES = SMEMU * 4;   // ~63.5 KB -> 2 CTAs/SM
static constexpr int OBUF = 0;       // epilogue scratch: 64 rows x 68 stride (in K region)

__device__ __forceinline__ void mma16(float* d, const uint32_t* a, uint32_t b0, uint32_t b1) {
    asm volatile(
        "mma.sync.aligned.m16n8k16.row.col.f32.f16.f16.f32 "
        "{%0,%1,%2,%3}, {%4,%5,%6,%7}, {%8,%9}, {%0,%1,%2,%3};"
        : "+f"(d[0]), "+f"(d[1]), "+f"(d[2]), "+f"(d[3])
        : "r"(a[0]), "r"(a[1]), "r"(a[2]), "r"(a[3]), "r"(b0), "r"(b1));
}

__device__ __forceinline__ uint32_t packhl(float x, float y, uint32_t& lo) {
    __half hx = __float2half_rn(x), hy = __float2half_rn(y);
    __half2 L = __floats2half2_rn(x - __half2float(hx), y - __half2float(hy));
    __half2 Hh = __halves2half2(hx, hy);
    lo = *(uint32_t*)&L;
    return *(uint32_t*)&Hh;
}

__device__ __forceinline__ uint32_t packh(float x, float y) {
    __half2 Hh = __floats2half2_rn(x, y);
    return *(uint32_t*)&Hh;
}

// V XOR swizzle (bits 1-4, bit0 untouched)
__device__ __forceinline__ int swzv(int h) {
    return ((h & 3) << 1) ^ (((h >> 2) & 7) << 2);
}

extern __shared__ uint32_t smu[];

__global__ void __launch_bounds__(NT, 2)
attn_h6(const float* __restrict__ q, const float* __restrict__ k,
        const float* __restrict__ v, const int* __restrict__ mask,
        float* __restrict__ out)
{
    const int tid = threadIdx.x;
    const int w = tid >> 5, lane = tid & 31;
    const int n_ = lane >> 2, tm = lane & 3;
    const int bx = blockIdx.x;
    const int b = bx >> 5, t0 = (bx & 31) << 6;     // 64-row tiles, 32 per batch
    const int slab = w & 3, shalf = w >> 2;         // 4 row-slabs x 2 s-halves

    const float* qb = q + ((size_t)b * T_ + t0) * H_;
    const float* kb = k + (size_t)b * S_ * H_;
    const float* vb = v + (size_t)b * S_ * H_;
    const int*   mb = mask + (size_t)b * S_;
    float* pp = out + (size_t)B_ * T_ * H_ + ((size_t)b * T_ + t0) * S_;
    float* oo = out + ((size_t)b * T_ + t0) * H_;

    float* smf = (float*)smu;
    unsigned short* cidx = (unsigned short*)(smu + CIDXU);
    const int prow = 16 * slab + n_;                // 0..63

    // ---- Q fragments: 4 k16-chunks, pre-split fp16 hi/lo, in registers ----
    uint32_t qh[4][4], ql[4][4];
    #pragma unroll
    for (int kc = 0; kc < 4; kc++) {
        const int base = kc * 16 + 2 * tm;
        float2 x0 = *(const float2*)(qb + prow * 64 + base);
        float2 x1 = *(const float2*)(qb + (prow + 8) * 64 + base);
        float2 x2 = *(const float2*)(qb + prow * 64 + base + 8);
        float2 x3 = *(const float2*)(qb + (prow + 8) * 64 + base + 8);
        qh[kc][0] = packhl(x0.x, x0.y, ql[kc][0]);
        qh[kc][1] = packhl(x1.x, x1.y, ql[kc][1]);
        qh[kc][2] = packhl(x2.x, x2.y, ql[kc][2]);
        qh[kc][3] = packhl(x3.x, x3.y, ql[kc][3]);
    }

    // ---- build compacted index of unmasked columns ----
    #pragma unroll
    for (int i = 0; i < 8; i++) {
        int s = i * 256 + tid;
        unsigned bal = __ballot_sync(0xffffffffu, mb[s] != 0);
        if (lane == 0) smu[BITARR + i * 8 + w] = bal;
    }
    __syncthreads();
    if (tid == 0) {
        int acc = 0;
        for (int c = 0; c < 64; c++) { smu[OFFU + c] = acc; acc += __popc(smu[BITARR + c]); }
        smu[SEFFU] = acc;
    }
    __syncthreads();
    const int seff = (int)smu[SEFFU];
    const int ntiles = (seff + 127) >> 7;
    const int npad = ntiles << 7;
    if (tid < 64) {
        uint32_t bits = smu[BITARR + tid];
        int o = (int)smu[OFFU + tid];
        int base = tid * 32;
        while (bits) { int bb = __ffs(bits) - 1; cidx[o++] = (unsigned short)(base + bb); bits &= bits - 1; }
    }
    for (int i = tid; i < npad; i += NT) if (i >= seff) cidx[i] = 0xFFFFu;

    float O[8][4];
    #pragma unroll
    for (int i = 0; i < 8; i++)
        #pragma unroll
        for (int jj = 0; jj < 4; jj++) O[i][jj] = 0.0f;
    float m0 = -3.0e38f, m1 = -3.0e38f, lm0 = 0.0f, lm1 = 0.0f;
    float em0 = 0.0f, em1 = 0.0f;
    const float LOGT = 10.0f;

    // K staging mapping
    const int ks_s  = tid >> 4;
    const int ks_k4 = (tid & 15) * 4;
    const int kt0 = ks_k4 >> 1;
    const int kpb = kt0 & ~7;
    const int ku0 = kt0 & 7;
    const int kp0 = kpb + 2 * (ku0 & 3) + (ku0 >> 2);
    const int kp1 = kp0 + 2;
    // V staging mapping
    const int vs_spb = w * 2 + (lane >> 4);
    const int vs_cc  = 4 * (lane & 15);

    for (int j = 0; j < ntiles; j++) {
        const int s0c = j << 7;
        __syncthreads();   // previous tile's reads complete (also orders index build)

        // ---- stage K (gathered): hi/lo fp16 pairs, pair-interleaved, stride 40 ----
        #pragma unroll
        for (int it = 0; it < 8; it++) {
            int s = ks_s + it * 16;
            int orig = cidx[s0c + s];
            float4 x = make_float4(0.f, 0.f, 0.f, 0.f);
            if (orig != 0xFFFF) x = *(const float4*)(kb + (size_t)orig * H_ + ks_k4);
            uint32_t l0, l1;
            uint32_t h0 = packhl(x.x, x.y, l0);
            uint32_t h1 = packhl(x.z, x.w, l1);
            smu[KHI + s * 40 + kp0] = h0;
            smu[KHI + s * 40 + kp1] = h1;
            smu[KLO + s * 40 + kp0] = l0;
            smu[KLO + s * 40 + kp1] = l1;
        }
        // ---- stage V (gathered): pack pairs, swizzled STS ----
        #pragma unroll
        for (int it = 0; it < 4; it++) {
            int sp = vs_spb + it * 16;
            int o0 = cidx[s0c + 2 * sp], o1 = cidx[s0c + 2 * sp + 1];
            float4 a  = make_float4(0.f, 0.f, 0.f, 0.f);
            float4 b4 = make_float4(0.f, 0.f, 0.f, 0.f);
            if (o0 != 0xFFFF) a  = *(const float4*)(vb + (size_t)o0 * H_ + vs_cc);
            if (o1 != 0xFFFF) b4 = *(const float4*)(vb + (size_t)o1 * H_ + vs_cc);
            int qp = (sp & ~7) + 2 * (sp & 3) + ((sp >> 2) & 1);
            smu[VHI + (vs_cc + 0) * 72 + (qp ^ swzv(vs_cc + 0))] = packh(a.x, b4.x);
            smu[VHI + (vs_cc + 1) * 72 + (qp ^ swzv(vs_cc + 1))] = packh(a.y, b4.y);
            smu[VHI + (vs_cc + 2) * 72 + (qp ^ swzv(vs_cc + 2))] = packh(a.z, b4.z);
            smu[VHI + (vs_cc + 3) * 72 + (qp ^ swzv(vs_cc + 3))] = packh(a.w, b4.w);
        }
        __syncthreads();

        // this warp handles strips [shalf*8, shalf*8+8) -> 4 strip-pairs
        #pragma unroll 2
        for (int ntp = 0; ntp < 4; ntp++) {
            const int ntpg = shalf * 4 + ntp;
            float sv[2][4];
            uint32_t bt[2][2];
            int co[2][2];
            // ---- raw QK^T scores for the two 8-col strips ----
            #pragma unroll
            for (int si = 0; si < 2; si++) {
                const int strip = ntpg * 2 + si;
                float dh[4] = {0.f,0.f,0.f,0.f}, dm[4] = {0.f,0.f,0.f,0.f}, dl[4] = {0.f,0.f,0.f,0.f};
                const int kb0 = (strip * 8 + n_) * 40 + 2 * tm;
                #pragma unroll
                for (int kc = 0; kc < 4; kc++) {
                    uint2 bh = *(const uint2*)&smu[KHI + kb0 + kc * 8];
                    uint2 bl = *(const uint2*)&smu[KLO + kb0 + kc * 8];
                    mma16(dh, qh[kc], bh.x, bh.y);
                    mma16(dm, ql[kc], bh.x, bh.y);
                    mma16(dl, qh[kc], bl.x, bl.y);
                }
                #pragma unroll
                for (int x = 0; x < 4; x++) sv[si][x] = dh[x] + dm[x] + dl[x];
                const int cg = strip * 8 + 2 * tm;
                uint32_t pr = *(const uint32_t*)&cidx[s0c + cg];
                co[si][0] = (int)(pr & 0xFFFFu);
                co[si][1] = (int)(pr >> 16);
                bt[si][0] = (co[si][0] != 0xFFFF);
                bt[si][1] = (co[si][1] != 0xFFFF);
            }
            // ---- per-lane max (padding excluded) for overflow check ----
            float t0_ = -3.0e38f, t1_ = -3.0e38f;
            #pragma unroll
            for (int si = 0; si < 2; si++) {
                if (bt[si][0]) { t0_ = fmaxf(t0_, sv[si][0]); t1_ = fmaxf(t1_, sv[si][2]); }
                if (bt[si][1]) { t0_ = fmaxf(t0_, sv[si][1]); t1_ = fmaxf(t1_, sv[si][3]); }
            }
            // ---- lazy max: exact slow path only when needed ----
            bool big = (t0_ > m0 + LOGT) || (t1_ > m1 + LOGT);
            if (__any_sync(0xffffffffu, big)) {
                t0_ = fmaxf(t0_, __shfl_xor_sync(0xffffffffu, t0_, 1));
                t0_ = fmaxf(t0_, __shfl_xor_sync(0xffffffffu, t0_, 2));
                t1_ = fmaxf(t1_, __shfl_xor_sync(0xffffffffu, t1_, 1));
                t1_ = fmaxf(t1_, __shfl_xor_sync(0xffffffffu, t1_, 2));
                float m0n = fmaxf(m0, t0_), m1n = fmaxf(m1, t1_);
                float f0 = __expf(m0 - m0n), f1 = __expf(m1 - m1n);
                lm0 *= f0; lm1 *= f1;
                #pragma unroll
                for (int vt = 0; vt < 8; vt++) {
                    O[vt][0] *= f0; O[vt][1] *= f0;
                    O[vt][2] *= f1; O[vt][3] *= f1;
                }
                m0 = m0n; m1 = m1n;
                em0 = __expf(m0); em1 = __expf(m1);
            }

            // ---- exp, scattered raw p store (= exp(s)), pack fp16 A-frags ----
            float e[2][4];
            #pragma unroll
            for (int si = 0; si < 2; si++) {
                e[si][0] = bt[si][0] ? __expf(sv[si][0] - m0) : 0.0f;
                e[si][1] = bt[si][1] ? __expf(sv[si][1] - m0) : 0.0f;
                e[si][2] = bt[si][0] ? __expf(sv[si][2] - m1) : 0.0f;
                e[si][3] = bt[si][1] ? __expf(sv[si][3] - m1) : 0.0f;
                lm0 += e[si][0] + e[si][1];
                lm1 += e[si][2] + e[si][3];
                if (bt[si][0]) {
                    pp[(size_t)prow * S_ + co[si][0]]       = e[si][0] * em0;
                    pp[(size_t)(prow + 8) * S_ + co[si][0]] = e[si][2] * em1;
                }
                if (bt[si][1]) {
                    pp[(size_t)prow * S_ + co[si][1]]       = e[si][1] * em0;
                    pp[(size_t)(prow + 8) * S_ + co[si][1]] = e[si][3] * em1;
                }
            }
            uint32_t pah[4], pal[4];
            pah[0] = packhl(e[0][0], e[0][1], pal[0]);
            pah[1] = packhl(e[0][2], e[0][3], pal[1]);
            pah[2] = packhl(e[1][0], e[1][1], pal[2]);
            pah[3] = packhl(e[1][2], e[1][3], pal[3]);

            // ---- PV: 8 independent O chains, V pairs via one LDS.64 each ----
            const int xbase = ntpg * 8 + 2 * tm;
            #pragma unroll
            for (int vt = 0; vt < 8; vt++) {
                const int h = vt * 8 + n_;
                uint2 vv = *(const uint2*)&smu[VHI + h * 72 + (xbase ^ swzv(h))];
                mma16(O[vt], pah, vv.x, vv.y);
                mma16(O[vt], pal, vv.x, vv.y);
            }
        }
    }

    // ================= epilogue: combine the two s-halves =================
    lm0 += __shfl_xor_sync(0xffffffffu, lm0, 1);
    lm0 += __shfl_xor_sync(0xffffffffu, lm0, 2);
    lm1 += __shfl_xor_sync(0xffffffffu, lm1, 1);
    lm1 += __shfl_xor_sync(0xffffffffu, lm1, 2);

    #pragma unroll
    for (int vt = 0; vt < 8; vt++) {
        O[vt][0] *= em0; O[vt][1] *= em0;
        O[vt][2] *= em1; O[vt][3] *= em1;
    }

    __syncthreads();   // done with K/V smem; reuse K region as OBUF
    if (tm == 0) {
        smf[LBUF + shalf * 64 + prow]     = lm0 * em0;
        smf[LBUF + shalf * 64 + prow + 8] = lm1 * em1;
    }
    if (shalf == 0) {
        #pragma unroll
        for (int vt = 0; vt < 8; vt++) {
            int c = vt * 8 + 2 * tm;
            *(float2*)&smf[OBUF + prow * 68 + c]       = make_float2(O[vt][0], O[vt][1]);
            *(float2*)&smf[OBUF + (prow + 8) * 68 + c] = make_float2(O[vt][2], O[vt][3]);
        }
    }
    __syncthreads();
    if (tid < 64) smf[RINV + tid] = 1.0f / (smf[LBUF + tid] + smf[LBUF + 64 + tid]);
    __syncthreads();

    if (shalf == 1) {
        const float iv0 = smf[RINV + prow];
        const float iv1 = smf[RINV + prow + 8];
        #pragma unroll
        for (int vt = 0; vt < 8; vt++) {
            int c = vt * 8 + 2 * tm;
            float2 pa = *(const float2*)&smf[OBUF + prow * 68 + c];
            float2 pb = *(const float2*)&smf[OBUF + (prow + 8) * 68 + c];
            *(float2*)(oo + (size_t)prow * H_ + c) =
                make_float2((pa.x + O[vt][0]) * iv0, (pa.y + O[vt][1]) * iv0);
            *(float2*)(oo + (size_t)(prow + 8) * H_ + c) =
                make_float2((pb.x + O[vt][2]) * iv1, (pb.y + O[vt][3]) * iv1);
        }
    }

    // ---- finalize p: scale unmasked, zero masked (fixes poison too) ----
    for (int i = tid; i < 64 * 512; i += NT) {
        int row = i >> 9, c4 = i & 511;
        float il = smf[RINV + row];
        uint32_t nib = (smu[BITARR + (c4 >> 3)] >> ((c4 & 7) * 4)) & 0xFu;
        float4* g = (float4*)(pp + (size_t)row * S_) + c4;
        float4 vv = __ldcs(g);
        vv.x = (nib & 1u) ? vv.x * il : 0.0f;
        vv.y = (nib & 2u) ? vv.y * il : 0.0f;
        vv.z = (nib & 4u) ? vv.z * il : 0.0f;
        vv.w = (nib & 8u) ? vv.w * il : 0.0f;
        __stcs(g, vv);
    }
}

extern "C" void kernel_launch(void* const* d_in, const int* in_sizes, int n_in,
                              void* d_out, int out_size)
{
    const float* q    = (const float*)d_in[0];
    const float* keys = (const float*)d_in[1];
    const float* vals = (const float*)d_in[2];
    const int*   mask = (const int*)d_in[3];
    float* out = (float*)d_out;

    cudaFuncSetAttribute(attn_h6, cudaFuncAttributeMaxDynamicSharedMemorySize, SMEM_BYTES);
    attn_h6<<<B_ * (T_ / 64), NT, SMEM_BYTES>>>(q, keys, vals, mask, out);
}

// round 13
// speedup vs baseline: 2.4760x; 1.1108x over previous
#include <cuda_runtime.h>
#include <cuda_fp16.h>
#include <cstdint>

static constexpr int B_ = 8, T_ = 2048, S_ = 2048, H_ = 64;
static constexpr int NT = 256;

// smem u32-unit offsets
static constexpr int KHI = 0;        // K hi: [s:128][pos:32] stride 40, pair-interleaved
static constexpr int KLO = 5120;
static constexpr int VHI = 10240;    // V hi: [h:64][pos:64] stride 72, interleave + XOR swizzle
static constexpr int CIDXU  = 14848; // 2176 u16 compacted col indices (1088 u32)
static constexpr int BITARR = 15936; // 64 u32 mask bits
static constexpr int OFFU   = 16000; // 64 u32 chunk offsets
static constexpr int RINV   = 16064; // 64 floats: 1/(L0+L1)
static constexpr int LBUF   = 16128; // 128 floats: L = lm*em per row per s-half
static constexpr int MBUF   = 16256; // 128 floats: m per row per s-half
static constexpr int MROWM  = 16384; // 64 floats: row m_ref
static constexpr int MROWC  = 16448; // 64 floats: row coef = exp(m_ref)/Ltot
static constexpr int SEFFU  = 16512;
static constexpr int SMEMU  = 16516;
static constexpr int SMEM_BYTES = SMEMU * 4;   // ~64.5 KB -> 2 CTAs/SM
static constexpr int OBUF = 0;       // epilogue scratch: 64 rows x 68 stride (in K region)

__device__ __forceinline__ void mma16(float* d, const uint32_t* a, uint32_t b0, uint32_t b1) {
    asm volatile(
        "mma.sync.aligned.m16n8k16.row.col.f32.f16.f16.f32 "
        "{%0,%1,%2,%3}, {%4,%5,%6,%7}, {%8,%9}, {%0,%1,%2,%3};"
        : "+f"(d[0]), "+f"(d[1]), "+f"(d[2]), "+f"(d[3])
        : "r"(a[0]), "r"(a[1]), "r"(a[2]), "r"(a[3]), "r"(b0), "r"(b1));
}

__device__ __forceinline__ uint32_t packhl(float x, float y, uint32_t& lo) {
    __half hx = __float2half_rn(x), hy = __float2half_rn(y);
    __half2 L = __floats2half2_rn(x - __half2float(hx), y - __half2float(hy));
    __half2 Hh = __halves2half2(hx, hy);
    lo = *(uint32_t*)&L;
    return *(uint32_t*)&Hh;
}

__device__ __forceinline__ uint32_t packh(float x, float y) {
    __half2 Hh = __floats2half2_rn(x, y);
    return *(uint32_t*)&Hh;
}

__device__ __forceinline__ int swzv(int h) {
    return ((h & 3) << 1) ^ (((h >> 2) & 7) << 2);
}

extern __shared__ uint32_t smu[];

__global__ void __launch_bounds__(NT, 2)
attn_h7(const float* __restrict__ q, const float* __restrict__ k,
        const float* __restrict__ v, const int* __restrict__ mask,
        float* __restrict__ out)
{
    const int tid = threadIdx.x;
    const int w = tid >> 5, lane = tid & 31;
    const int n_ = lane >> 2, tm = lane & 3;
    const int bx = blockIdx.x;
    const int b = bx >> 5, t0 = (bx & 31) << 6;
    const int slab = w & 3, shalf = w >> 2;

    const float* qb = q + ((size_t)b * T_ + t0) * H_;
    const float* kb = k + (size_t)b * S_ * H_;
    const float* vb = v + (size_t)b * S_ * H_;
    const int*   mb = mask + (size_t)b * S_;
    float* pp = out + (size_t)B_ * T_ * H_ + ((size_t)b * T_ + t0) * S_;
    float* oo = out + ((size_t)b * T_ + t0) * H_;

    float* smf = (float*)smu;
    unsigned short* cidx = (unsigned short*)(smu + CIDXU);
    const int prow = 16 * slab + n_;

    // ---- Q fragments: fp16 hi/lo, resident ----
    uint32_t qh[4][4], ql[4][4];
    #pragma unroll
    for (int kc = 0; kc < 4; kc++) {
        const int base = kc * 16 + 2 * tm;
        float2 x0 = *(const float2*)(qb + prow * 64 + base);
        float2 x1 = *(const float2*)(qb + (prow + 8) * 64 + base);
        float2 x2 = *(const float2*)(qb + prow * 64 + base + 8);
        float2 x3 = *(const float2*)(qb + (prow + 8) * 64 + base + 8);
        qh[kc][0] = packhl(x0.x, x0.y, ql[kc][0]);
        qh[kc][1] = packhl(x1.x, x1.y, ql[kc][1]);
        qh[kc][2] = packhl(x2.x, x2.y, ql[kc][2]);
        qh[kc][3] = packhl(x3.x, x3.y, ql[kc][3]);
    }

    // ---- build mask bits + compacted index ----
    #pragma unroll
    for (int i = 0; i < 8; i++) {
        int s = i * 256 + tid;
        unsigned bal = __ballot_sync(0xffffffffu, mb[s] != 0);
        if (lane == 0) smu[BITARR + i * 8 + w] = bal;
    }
    __syncthreads();
    if (tid == 0) {
        int acc = 0;
        for (int c = 0; c < 64; c++) { smu[OFFU + c] = acc; acc += __popc(smu[BITARR + c]); }
        smu[SEFFU] = acc;
    }
    __syncthreads();
    const int seff = (int)smu[SEFFU];
    const int ntiles = (seff + 127) >> 7;
    const int npad = ntiles << 7;
    if (tid < 64) {
        uint32_t bits = smu[BITARR + tid];
        int o = (int)smu[OFFU + tid];
        int base = tid * 32;
        while (bits) { int bb = __ffs(bits) - 1; cidx[o++] = (unsigned short)(base + bb); bits &= bits - 1; }
    }
    for (int i = tid; i < npad; i += NT) if (i >= seff) cidx[i] = 0xFFFFu;

    float O[8][4];
    #pragma unroll
    for (int i = 0; i < 8; i++)
        #pragma unroll
        for (int jj = 0; jj < 4; jj++) O[i][jj] = 0.0f;
    float m0 = -3.0e38f, m1 = -3.0e38f, lm0 = 0.0f, lm1 = 0.0f;
    float em0 = 0.0f, em1 = 0.0f;
    const float LOGT = 10.0f;

    // staging mappings
    const int ks_s  = tid >> 4;
    const int ks_k4 = (tid & 15) * 4;
    const int kt0 = ks_k4 >> 1;
    const int kpb = kt0 & ~7;
    const int ku0 = kt0 & 7;
    const int kp0 = kpb + 2 * (ku0 & 3) + (ku0 >> 2);
    const int kp1 = kp0 + 2;
    const int vs_spb = w * 2 + (lane >> 4);
    const int vs_cc  = 4 * (lane & 15);

    // =================== PHASE A: compacted, stats + O (no p stores) ===================
    for (int j = 0; j < ntiles; j++) {
        const int s0c = j << 7;
        __syncthreads();

        #pragma unroll
        for (int it = 0; it < 8; it++) {
            int s = ks_s + it * 16;
            int orig = cidx[s0c + s];
            float4 x = make_float4(0.f, 0.f, 0.f, 0.f);
            if (orig != 0xFFFF) x = *(const float4*)(kb + (size_t)orig * H_ + ks_k4);
            uint32_t l0, l1;
            uint32_t h0 = packhl(x.x, x.y, l0);
            uint32_t h1 = packhl(x.z, x.w, l1);
            smu[KHI + s * 40 + kp0] = h0;
            smu[KHI + s * 40 + kp1] = h1;
            smu[KLO + s * 40 + kp0] = l0;
            smu[KLO + s * 40 + kp1] = l1;
        }
        #pragma unroll
        for (int it = 0; it < 4; it++) {
            int sp = vs_spb + it * 16;
            int o0 = cidx[s0c + 2 * sp], o1 = cidx[s0c + 2 * sp + 1];
            float4 a  = make_float4(0.f, 0.f, 0.f, 0.f);
            float4 b4 = make_float4(0.f, 0.f, 0.f, 0.f);
            if (o0 != 0xFFFF) a  = *(const float4*)(vb + (size_t)o0 * H_ + vs_cc);
            if (o1 != 0xFFFF) b4 = *(const float4*)(vb + (size_t)o1 * H_ + vs_cc);
            int qp = (sp & ~7) + 2 * (sp & 3) + ((sp >> 2) & 1);
            smu[VHI + (vs_cc + 0) * 72 + (qp ^ swzv(vs_cc + 0))] = packh(a.x, b4.x);
            smu[VHI + (vs_cc + 1) * 72 + (qp ^ swzv(vs_cc + 1))] = packh(a.y, b4.y);
            smu[VHI + (vs_cc + 2) * 72 + (qp ^ swzv(vs_cc + 2))] = packh(a.z, b4.z);
            smu[VHI + (vs_cc + 3) * 72 + (qp ^ swzv(vs_cc + 3))] = packh(a.w, b4.w);
        }
        __syncthreads();

        #pragma unroll 2
        for (int ntp = 0; ntp < 4; ntp++) {
            const int ntpg = shalf * 4 + ntp;
            float sv[2][4];
            bool bt[2][2];
            #pragma unroll
            for (int si = 0; si < 2; si++) {
                const int strip = ntpg * 2 + si;
                float dh[4] = {0.f,0.f,0.f,0.f}, dm[4] = {0.f,0.f,0.f,0.f}, dl[4] = {0.f,0.f,0.f,0.f};
                const int kb0 = (strip * 8 + n_) * 40 + 2 * tm;
                #pragma unroll
                for (int kc = 0; kc < 4; kc++) {
                    uint2 bh = *(const uint2*)&smu[KHI + kb0 + kc * 8];
                    uint2 bl = *(const uint2*)&smu[KLO + kb0 + kc * 8];
                    mma16(dh, qh[kc], bh.x, bh.y);
                    mma16(dm, ql[kc], bh.x, bh.y);
                    mma16(dl, qh[kc], bl.x, bl.y);
                }
                #pragma unroll
                for (int x = 0; x < 4; x++) sv[si][x] = dh[x] + dm[x] + dl[x];
                const int cg = strip * 8 + 2 * tm;
                uint32_t pr = *(const uint32_t*)&cidx[s0c + cg];
                bt[si][0] = ((pr & 0xFFFFu) != 0xFFFFu);
                bt[si][1] = ((pr >> 16) != 0xFFFFu);
            }
            float t0_ = -3.0e38f, t1_ = -3.0e38f;
            #pragma unroll
            for (int si = 0; si < 2; si++) {
                if (bt[si][0]) { t0_ = fmaxf(t0_, sv[si][0]); t1_ = fmaxf(t1_, sv[si][2]); }
                if (bt[si][1]) { t0_ = fmaxf(t0_, sv[si][1]); t1_ = fmaxf(t1_, sv[si][3]); }
            }
            bool big = (t0_ > m0 + LOGT) || (t1_ > m1 + LOGT);
            if (__any_sync(0xffffffffu, big)) {
                t0_ = fmaxf(t0_, __shfl_xor_sync(0xffffffffu, t0_, 1));
                t0_ = fmaxf(t0_, __shfl_xor_sync(0xffffffffu, t0_, 2));
                t1_ = fmaxf(t1_, __shfl_xor_sync(0xffffffffu, t1_, 1));
                t1_ = fmaxf(t1_, __shfl_xor_sync(0xffffffffu, t1_, 2));
                float m0n = fmaxf(m0, t0_), m1n = fmaxf(m1, t1_);
                float f0 = __expf(m0 - m0n), f1 = __expf(m1 - m1n);
                lm0 *= f0; lm1 *= f1;
                #pragma unroll
                for (int vt = 0; vt < 8; vt++) {
                    O[vt][0] *= f0; O[vt][1] *= f0;
                    O[vt][2] *= f1; O[vt][3] *= f1;
                }
                m0 = m0n; m1 = m1n;
                em0 = __expf(m0); em1 = __expf(m1);
            }

            float e[2][4];
            #pragma unroll
            for (int si = 0; si < 2; si++) {
                e[si][0] = bt[si][0] ? __expf(sv[si][0] - m0) : 0.0f;
                e[si][1] = bt[si][1] ? __expf(sv[si][1] - m0) : 0.0f;
                e[si][2] = bt[si][0] ? __expf(sv[si][2] - m1) : 0.0f;
                e[si][3] = bt[si][1] ? __expf(sv[si][3] - m1) : 0.0f;
                lm0 += e[si][0] + e[si][1];
                lm1 += e[si][2] + e[si][3];
            }
            uint32_t pah[4], pal[4];
            pah[0] = packhl(e[0][0], e[0][1], pal[0]);
            pah[1] = packhl(e[0][2], e[0][3], pal[1]);
            pah[2] = packhl(e[1][0], e[1][1], pal[2]);
            pah[3] = packhl(e[1][2], e[1][3], pal[3]);

            const int xbase = ntpg * 8 + 2 * tm;
            #pragma unroll
            for (int vt = 0; vt < 8; vt++) {
                const int h = vt * 8 + n_;
                uint2 vv = *(const uint2*)&smu[VHI + h * 72 + (xbase ^ swzv(h))];
                mma16(O[vt], pah, vv.x, vv.y);
                mma16(O[vt], pal, vv.x, vv.y);
            }
        }
    }

    // =================== epilogue: combine halves, write O, row coefs ===================
    lm0 += __shfl_xor_sync(0xffffffffu, lm0, 1);
    lm0 += __shfl_xor_sync(0xffffffffu, lm0, 2);
    lm1 += __shfl_xor_sync(0xffffffffu, lm1, 1);
    lm1 += __shfl_xor_sync(0xffffffffu, lm1, 2);

    #pragma unroll
    for (int vt = 0; vt < 8; vt++) {
        O[vt][0] *= em0; O[vt][1] *= em0;
        O[vt][2] *= em1; O[vt][3] *= em1;
    }

    __syncthreads();   // done with K/V smem; reuse K region as OBUF
    if (tm == 0) {
        smf[LBUF + shalf * 64 + prow]     = lm0 * em0;
        smf[LBUF + shalf * 64 + prow + 8] = lm1 * em1;
        smf[MBUF + shalf * 64 + prow]     = m0;
        smf[MBUF + shalf * 64 + prow + 8] = m1;
    }
    if (shalf == 0) {
        #pragma unroll
        for (int vt = 0; vt < 8; vt++) {
            int c = vt * 8 + 2 * tm;
            *(float2*)&smf[OBUF + prow * 68 + c]       = make_float2(O[vt][0], O[vt][1]);
            *(float2*)&smf[OBUF + (prow + 8) * 68 + c] = make_float2(O[vt][2], O[vt][3]);
        }
    }
    __syncthreads();
    if (tid < 64) {
        float inv = 1.0f / (smf[LBUF + tid] + smf[LBUF + 64 + tid]);
        smf[RINV + tid] = inv;
        float mr = fmaxf(smf[MBUF + tid], smf[MBUF + 64 + tid]);
        smf[MROWM + tid] = mr;
        smf[MROWC + tid] = __expf(mr) * inv;
    }
    __syncthreads();

    if (shalf == 1) {
        const float iv0 = smf[RINV + prow];
        const float iv1 = smf[RINV + prow + 8];
        #pragma unroll
        for (int vt = 0; vt < 8; vt++) {
            int c = vt * 8 + 2 * tm;
            float2 pa = *(const float2*)&smf[OBUF + prow * 68 + c];
            float2 pb = *(const float2*)&smf[OBUF + (prow + 8) * 68 + c];
            *(float2*)(oo + (size_t)prow * H_ + c) =
                make_float2((pa.x + O[vt][0]) * iv0, (pa.y + O[vt][1]) * iv0);
            *(float2*)(oo + (size_t)(prow + 8) * H_ + c) =
                make_float2((pb.x + O[vt][2]) * iv1, (pb.y + O[vt][3]) * iv1);
        }
    }

    // =================== PHASE B: original space, write final p once ===================
    const float mr0 = smf[MROWM + prow],     cf0 = smf[MROWC + prow];
    const float mr1 = smf[MROWM + prow + 8], cf1 = smf[MROWC + prow + 8];

    for (int j = 0; j < 16; j++) {
        const int s0 = j << 7;
        __syncthreads();   // previous tile reads done (also protects OBUF in K region)

        // stage K (hi/lo), contiguous original rows
        const float* kt = kb + (size_t)s0 * H_;
        #pragma unroll
        for (int it = 0; it < 8; it++) {
            int s = ks_s + it * 16;
            float4 x = *(const float4*)(kt + s * 64 + ks_k4);
            uint32_t l0, l1;
            uint32_t h0 = packhl(x.x, x.y, l0);
            uint32_t h1 = packhl(x.z, x.w, l1);
            smu[KHI + s * 40 + kp0] = h0;
            smu[KHI + s * 40 + kp1] = h1;
            smu[KLO + s * 40 + kp0] = l0;
            smu[KLO + s * 40 + kp1] = l1;
        }
        __syncthreads();

        #pragma unroll 2
        for (int ntp = 0; ntp < 4; ntp++) {
            const int ntpg = shalf * 4 + ntp;
            #pragma unroll
            for (int si = 0; si < 2; si++) {
                const int strip = ntpg * 2 + si;
                float dh[4] = {0.f,0.f,0.f,0.f}, dm[4] = {0.f,0.f,0.f,0.f}, dl[4] = {0.f,0.f,0.f,0.f};
                const int kb0 = (strip * 8 + n_) * 40 + 2 * tm;
                #pragma unroll
                for (int kc = 0; kc < 4; kc++) {
                    uint2 bh = *(const uint2*)&smu[KHI + kb0 + kc * 8];
                    uint2 bl = *(const uint2*)&smu[KLO + kb0 + kc * 8];
                    mma16(dh, qh[kc], bh.x, bh.y);
                    mma16(dm, ql[kc], bh.x, bh.y);
                    mma16(dl, qh[kc], bl.x, bl.y);
                }
                const int cg = strip * 8 + 2 * tm;
                uint32_t wb = smu[BITARR + j * 4 + (strip >> 2)];
                int sh = ((strip & 3) << 3) + 2 * tm;
                bool b0 = (wb >> sh) & 1u, b1 = (wb >> (sh + 1)) & 1u;
                float s00 = dh[0] + dm[0] + dl[0];
                float s01 = dh[1] + dm[1] + dl[1];
                float s10 = dh[2] + dm[2] + dl[2];
                float s11 = dh[3] + dm[3] + dl[3];
                float p00 = b0 ? __expf(s00 - mr0) * cf0 : 0.0f;
                float p01 = b1 ? __expf(s01 - mr0) * cf0 : 0.0f;
                float p10 = b0 ? __expf(s10 - mr1) * cf1 : 0.0f;
                float p11 = b1 ? __expf(s11 - mr1) * cf1 : 0.0f;
                __stcs((float2*)(pp + (size_t)prow * S_ + s0 + cg), make_float2(p00, p01));
                __stcs((float2*)(pp + (size_t)(prow + 8) * S_ + s0 + cg), make_float2(p10, p11));
            }
        }
    }
}

extern "C" void kernel_launch(void* const* d_in, const int* in_sizes, int n_in,
                              void* d_out, int out_size)
{
    const float* q    = (const float*)d_in[0];
    const float* keys = (const float*)d_in[1];
    const float* vals = (const float*)d_in[2];
    const int*   mask = (const int*)d_in[3];
    float* out = (float*)d_out;

    cudaFuncSetAttribute(attn_h7, cudaFuncAttributeMaxDynamicSharedMemorySize, SMEM_BYTES);
    attn_h7<<<B_ * (T_ / 64), NT, SMEM_BYTES>>>(q, keys, vals, mask, out);
}